// round 10
// baseline (speedup 1.0000x reference)
#include <cuda_runtime.h>
#include <cuda_fp16.h>
#include <cstdint>

#define D        256
#define KCODES   1024
#define BM       128
#define THETA    0.18f
#define DYN_SMEM 110592

// ---- device scratch (no allocations allowed) ----
__device__ uint32_t g_epack[KCODES * 128];   // per code: 256 fp16 (512B)
__device__ float    g_e_half[KCODES];
__device__ float    g_counts[KCODES];
__device__ int      g_flag_rows[131072];     // row | (full<<30)
__device__ int      g_flag_pair[131072];     // i1 | (i2<<16)
__device__ int      g_flag_cnt;
__device__ double   g_loss;

// ============================ helpers ============================
__device__ __forceinline__ uint32_t smem_u32(const void* p) {
    uint32_t a;
    asm("{ .reg .u64 t; cvta.to.shared.u64 t, %1; cvt.u32.u64 %0, t; }" : "=r"(a) : "l"(p));
    return a;
}

__device__ __forceinline__ void ldsm_x4(uint32_t& r0, uint32_t& r1, uint32_t& r2, uint32_t& r3,
                                        uint32_t addr) {
    asm volatile("ldmatrix.sync.aligned.m8n8.x4.shared.b16 {%0,%1,%2,%3}, [%4];"
                 : "=r"(r0), "=r"(r1), "=r"(r2), "=r"(r3) : "r"(addr));
}

__device__ __forceinline__ void mma_f16(float* c, const uint32_t* a, uint32_t b0, uint32_t b1) {
    asm volatile("mma.sync.aligned.m16n8k16.row.col.f32.f16.f16.f32 "
                 "{%0,%1,%2,%3}, {%4,%5,%6,%7}, {%8,%9}, {%0,%1,%2,%3};"
                 : "+f"(c[0]), "+f"(c[1]), "+f"(c[2]), "+f"(c[3])
                 : "r"(a[0]), "r"(a[1]), "r"(a[2]), "r"(a[3]), "r"(b0), "r"(b1));
}

#define CP_ASYNC16(dst, src) \
    asm volatile("cp.async.cg.shared.global [%0], [%1], 16;" :: "r"(dst), "l"(src) : "memory")
#define CP_COMMIT() asm volatile("cp.async.commit_group;" ::: "memory")
#define CP_WAIT_ALL() asm volatile("cp.async.wait_group 0;" ::: "memory")

// merge top-3 (with indices for top-2); ties prefer lower index
__device__ __forceinline__ void merge3(float& m1, int& i1, float& m2, int& i2, float& m3,
                                       float b1, int j1, float b2, int j2, float b3) {
    float n1, n2, n3; int k1, k2;
    if (b1 < m1 || (b1 == m1 && j1 < i1)) {
        n1 = b1; k1 = j1;
        if (m1 < b2 || (m1 == b2 && i1 < j2)) { n2 = m1; k2 = i1; n3 = fminf(b2, m2); }
        else                                   { n2 = b2; k2 = j2; n3 = fminf(m1, b3); }
    } else {
        n1 = m1; k1 = i1;
        if (b1 < m2 || (b1 == m2 && j1 < i2)) { n2 = b1; k2 = j1; n3 = fminf(m2, b2); }
        else                                   { n2 = m2; k2 = i2; n3 = fminf(b1, m3); }
    }
    m1 = n1; i1 = k1; m2 = n2; i2 = k2; m3 = n3;
}

#define UPD3(sl, sval, scol) do { \
    float _s = (sval); \
    if (_s < M1[sl])      { M3[sl] = M2[sl]; M2[sl] = M1[sl]; I2[sl] = I1[sl]; M1[sl] = _s; I1[sl] = (scol); } \
    else if (_s < M2[sl]) { M3[sl] = M2[sl]; M2[sl] = _s; I2[sl] = (scol); } \
    else if (_s < M3[sl]) { M3[sl] = _s; } \
} while (0)

// ============================ kernels ============================
__global__ void noop_kernel() {}

// One warp per code: pack 256 fp16 + 0.5*||e||^2 ; also reset globals
__global__ void prep_kernel(const float* __restrict__ e) {
    int tid  = threadIdx.x;
    int gw   = (blockIdx.x * blockDim.x + tid) >> 5;
    int lane = tid & 31;
    if (blockIdx.x < 4) g_counts[blockIdx.x * 256 + tid] = 0.0f;
    if (blockIdx.x == 0 && tid == 0) { g_loss = 0.0; g_flag_cnt = 0; }
    if (gw >= KCODES) return;
    const float4* er = (const float4*)(e + (size_t)gw * D);
    float4 a = er[lane * 2];
    float4 b = er[lane * 2 + 1];
    __half2 h0 = __floats2half2_rn(a.x, a.y);
    __half2 h1 = __floats2half2_rn(a.z, a.w);
    __half2 h2 = __floats2half2_rn(b.x, b.y);
    __half2 h3 = __floats2half2_rn(b.z, b.w);
    uint4 u;
    u.x = *(uint32_t*)&h0; u.y = *(uint32_t*)&h1;
    u.z = *(uint32_t*)&h2; u.w = *(uint32_t*)&h3;
    *(uint4*)&g_epack[gw * 128 + lane * 4] = u;
    float s = a.x*a.x + a.y*a.y + a.z*a.z + a.w*a.w
            + b.x*b.x + b.y*b.y + b.z*b.z + b.w*b.w;
    #pragma unroll
    for (int o = 16; o > 0; o >>= 1) s += __shfl_down_sync(0xffffffffu, s, o);
    if (lane == 0) g_e_half[gw] = 0.5f * s;
}

// load one B chunk (128 codes x 128B of k) with XOR swizzle; one cp.async group
__device__ __forceinline__ void load_chunk(uint32_t dstb, int gi, int tid) {
    const char* src0 = (const char*)g_epack + (size_t)(gi >> 2) * 65536 + (size_t)(gi & 3) * 128;
    #pragma unroll
    for (int it = 0; it < 4; ++it) {
        int i = it * 256 + tid;           // 1024 16B units
        int r = i >> 3, s = i & 7;
        uint32_t ps = (uint32_t)s ^ ((uint32_t)r & 7u);
        CP_ASYNC16(dstb + (uint32_t)r * 128u + ps * 16u, src0 + (size_t)r * 512 + s * 16);
    }
    CP_COMMIT();
}

__global__ __launch_bounds__(256, 2) void vq_main(const float* __restrict__ z,
                                                  const float* __restrict__ e,
                                                  float* __restrict__ outq) {
    extern __shared__ char dsm[];
    char* base = (char*)(((uintptr_t)dsm + 1023) & ~(uintptr_t)1023);
    char*  sA   = base;                       // 65536 : 128 rows x 256 fp16 (swizzled)
    char*  sB   = base + 65536;               // 2 x 16384
    float* s_eh = (float*)(base + 98304);     // 1024 f
    float* rm1  = (float*)(base + 102400);    // 128 x 2
    float* rm2  = (float*)(base + 103424);
    float* rm3  = (float*)(base + 104448);
    int*   ri1  = (int*)  (base + 105472);
    int*   ri2  = (int*)  (base + 106496);
    int*   sidx = (int*)  (base + 107520);    // 128
    int*   sflg = (int*)  (base + 108032);    // 128
    float* red  = (float*)(base + 108544);    // 256 f

    const int tid  = threadIdx.x;
    const int lane = tid & 31;
    const int w    = tid >> 5;
    const int wm   = w >> 1;   // 0..3 : M warp (32 rows)
    const int wn   = w & 1;    // 0..1 : N warp (64 cols)
    const int rowbase = blockIdx.x * BM;
    const uint32_t sAu = smem_u32(sA);
    const uint32_t sBu = smem_u32(sB);

    // prologue: first two B chunks
    load_chunk(sBu,          0, tid);
    load_chunk(sBu + 16384u, 1, tid);

    for (int i = tid; i < KCODES; i += 256) s_eh[i] = g_e_half[i];

    // ---- convert this CTA's 128 z rows into swizzled fp16 SMEM A ----
    const float4* zb = (const float4*)(z + (size_t)rowbase * D);
    #pragma unroll
    for (int i = 0; i < 32; ++i) {
        int idx = i * 256 + tid;           // 8192 float4s
        int r = idx >> 6, f = idx & 63;
        float4 v = zb[r * 64 + f];
        __half2 p0 = __floats2half2_rn(v.x, v.y);
        __half2 p1 = __floats2half2_rn(v.z, v.w);
        uint2 u; u.x = *(uint32_t*)&p0; u.y = *(uint32_t*)&p1;
        uint32_t seg = (uint32_t)(f >> 1);
        uint32_t ps = (seg & ~7u) | ((seg & 7u) ^ ((uint32_t)r & 7u));
        *(uint2*)(sA + (size_t)r * 512 + ps * 16 + (f & 1) * 8) = u;
    }
    __syncthreads();

    const float INF = __int_as_float(0x7f800000);
    float M1[4], M2[4], M3[4];
    int   I1[4], I2[4];
    #pragma unroll
    for (int s = 0; s < 4; ++s) { M1[s] = INF; M2[s] = INF; M3[s] = INF; I1[s] = 0; I2[s] = 0; }

    float acc[2][4][2][4];

    // ---- pipeline over 32 B chunks (8 nt x 4 c) ----
    #pragma unroll 1
    for (int g = 0; g < 32; ++g) {
        int c = g & 3;
        if (c == 0) {
            #pragma unroll
            for (int a = 0; a < 2; ++a)
                #pragma unroll
                for (int p = 0; p < 4; ++p)
                    #pragma unroll
                    for (int q = 0; q < 2; ++q)
                        #pragma unroll
                        for (int x = 0; x < 4; ++x) acc[a][p][q][x] = 0.0f;
        }
        CP_WAIT_ALL();
        __syncthreads();     // chunk g visible; all warps done with chunk g-1
        if (g >= 1 && g + 1 < 32)
            load_chunk(sBu + (uint32_t)((g + 1) & 1) * 16384u, g + 1, tid);

        uint32_t bufo = (uint32_t)(g & 1) * 16384u;

        #pragma unroll
        for (int ks = 0; ks < 4; ++ks) {
            uint32_t bfr[4][4];
            #pragma unroll
            for (int p = 0; p < 4; ++p) {
                int br = wn * 64 + p * 16 + (lane & 7) + ((lane >> 4) & 1) * 8;
                uint32_t ls = (uint32_t)(ks * 2) + (uint32_t)((lane >> 3) & 1);
                uint32_t ps = ls ^ ((uint32_t)br & 7u);
                ldsm_x4(bfr[p][0], bfr[p][1], bfr[p][2], bfr[p][3],
                        sBu + bufo + (uint32_t)br * 128u + ps * 16u);
            }
            uint32_t afr[2][4];
            uint32_t kbyte = (uint32_t)(c * 128 + ks * 32);
            #pragma unroll
            for (int mf = 0; mf < 2; ++mf) {
                int ar = wm * 32 + mf * 16 + (lane & 15);
                uint32_t seg = (kbyte >> 4) + (uint32_t)(lane >> 4);
                uint32_t ps = (seg & ~7u) | ((seg & 7u) ^ ((uint32_t)ar & 7u));
                ldsm_x4(afr[mf][0], afr[mf][1], afr[mf][2], afr[mf][3],
                        sAu + (uint32_t)ar * 512u + ps * 16u);
            }
            #pragma unroll
            for (int p = 0; p < 4; ++p) {
                mma_f16(acc[0][p][0], afr[0], bfr[p][0], bfr[p][1]);
                mma_f16(acc[0][p][1], afr[0], bfr[p][2], bfr[p][3]);
                mma_f16(acc[1][p][0], afr[1], bfr[p][0], bfr[p][1]);
                mma_f16(acc[1][p][1], afr[1], bfr[p][2], bfr[p][3]);
            }
        }

        if (c == 3) {
            int ntb = (g >> 2) * 128 + wn * 64;
            #pragma unroll
            for (int mf = 0; mf < 2; ++mf)
                #pragma unroll
                for (int p = 0; p < 4; ++p)
                    #pragma unroll
                    for (int q = 0; q < 2; ++q) {
                        int colb = ntb + p * 16 + q * 8 + (lane & 3) * 2;
                        float e0 = s_eh[colb], e1 = s_eh[colb + 1];
                        UPD3(mf * 2 + 0, e0 - acc[mf][p][q][0], colb);
                        UPD3(mf * 2 + 0, e1 - acc[mf][p][q][1], colb + 1);
                        UPD3(mf * 2 + 1, e0 - acc[mf][p][q][2], colb);
                        UPD3(mf * 2 + 1, e1 - acc[mf][p][q][3], colb + 1);
                    }
        }
    }

    // ---- reduce across the 4 lanes sharing each row ----
    #pragma unroll
    for (int sl = 0; sl < 4; ++sl) {
        float m1 = M1[sl], m2 = M2[sl], m3 = M3[sl];
        int i1 = I1[sl], i2 = I2[sl];
        #pragma unroll
        for (int o = 1; o <= 2; o <<= 1) {
            float b1 = __shfl_xor_sync(0xffffffffu, m1, o);
            float b2 = __shfl_xor_sync(0xffffffffu, m2, o);
            float b3 = __shfl_xor_sync(0xffffffffu, m3, o);
            int   j1 = __shfl_xor_sync(0xffffffffu, i1, o);
            int   j2 = __shfl_xor_sync(0xffffffffu, i2, o);
            merge3(m1, i1, m2, i2, m3, b1, j1, b2, j2, b3);
        }
        if ((lane & 3) == 0) {
            int row = wm * 32 + (sl >> 1) * 16 + (sl & 1) * 8 + (lane >> 2);
            int ent = row * 2 + wn;
            rm1[ent] = m1; rm2[ent] = m2; rm3[ent] = m3;
            ri1[ent] = i1; ri2[ent] = i2;
        }
    }
    __syncthreads();

    if (tid < BM) {
        float m1 = rm1[tid * 2], m2 = rm2[tid * 2], m3 = rm3[tid * 2];
        int   i1 = ri1[tid * 2], i2 = ri2[tid * 2];
        merge3(m1, i1, m2, i2, m3,
               rm1[tid * 2 + 1], ri1[tid * 2 + 1],
               rm2[tid * 2 + 1], ri2[tid * 2 + 1], rm3[tid * 2 + 1]);
        int pairf = (m2 - m1 < THETA) ? 1 : 0;
        int fullf = (m3 - m1 < THETA) ? 1 : 0;
        sidx[tid] = i1;
        sflg[tid] = pairf;
        if (pairf) {
            int p = atomicAdd(&g_flag_cnt, 1);
            g_flag_rows[p] = (rowbase + tid) | (fullf << 30);
            g_flag_pair[p] = i1 | (i2 << 16);
        } else {
            atomicAdd(&g_counts[i1], 1.0f);
        }
    }
    __syncthreads();

    // ---- fused output: gather + loss for non-flagged rows ----
    float lacc = 0.0f;
    #pragma unroll 4
    for (int p = tid; p < BM * D; p += 256) {
        int r = p >> 8;
        int cc = p & 255;
        if (!sflg[r]) {
            float q  = e[(size_t)sidx[r] * D + cc];
            float zv = z[(size_t)(rowbase + r) * D + cc];
            outq[(size_t)(rowbase + r) * D + cc] = q;
            float d = q - zv;
            lacc += d * d;
        }
    }
    red[tid] = lacc;
    __syncthreads();
    for (int o = 128; o > 32; o >>= 1) {
        if (tid < o) red[tid] += red[tid + o];
        __syncthreads();
    }
    if (tid < 32) {
        float v = red[tid] + red[tid + 32];
        #pragma unroll
        for (int o = 16; o > 0; o >>= 1) v += __shfl_down_sync(0xffffffffu, v, o);
        if (tid == 0) atomicAdd(&g_loss, (double)v);
    }
}

// exact fp32 rescue: pair-compare (common) or full rescan (rare), then output row
__global__ __launch_bounds__(256) void rescue_kernel(const float* __restrict__ z,
                                                     const float* __restrict__ e,
                                                     float* __restrict__ outq) {
    __shared__ float zs[256];
    __shared__ float rbv[8];
    __shared__ int   rbi[8];
    __shared__ int   s_best;
    __shared__ float red[256];
    int cnt = g_flag_cnt;
    int tid = threadIdx.x, w = tid >> 5, lane = tid & 31;
    for (int ri = blockIdx.x; ri < cnt; ri += gridDim.x) {
        int rowp = g_flag_rows[ri];
        int row  = rowp & 0x3fffffff;
        int full = (rowp >> 30) & 1;
        int pair = g_flag_pair[ri];
        if (tid < 64) ((float4*)zs)[tid] = ((const float4*)(z + (size_t)row * D))[tid];
        __syncthreads();
        float4 za = ((const float4*)zs)[lane];
        float4 zc = ((const float4*)zs)[lane + 32];

        if (!full) {
            // exact fp32 scores for the two candidates; warps 0 and 1
            if (w < 2) {
                int c = (w == 0) ? (pair & 0xffff) : (pair >> 16);
                const float4* er = (const float4*)(e + (size_t)c * D);
                float4 a0 = er[lane], b0 = er[lane + 32];
                float d0 = a0.x*za.x + a0.y*za.y + a0.z*za.z + a0.w*za.w
                         + b0.x*zc.x + b0.y*zc.y + b0.z*zc.z + b0.w*zc.w;
                #pragma unroll
                for (int o = 16; o > 0; o >>= 1) d0 += __shfl_xor_sync(0xffffffffu, d0, o);
                if (lane == 0) { rbv[w] = g_e_half[c] - d0; rbi[w] = c; }
            }
            __syncthreads();
            if (tid == 0) {
                float v0 = rbv[0], v1 = rbv[1];
                int   c0 = rbi[0], c1 = rbi[1];
                int best = (v1 < v0 || (v1 == v0 && c1 < c0)) ? c1 : c0;
                s_best = best;
                atomicAdd(&g_counts[best], 1.0f);
            }
        } else {
            // full exact rescan
            float bm = __int_as_float(0x7f800000);
            int   bi = KCODES;
            int wbase = w * 128;
            #pragma unroll 1
            for (int k = 0; k < 128; k += 2) {
                int c0 = wbase + k, c1 = c0 + 1;
                const float4* e0 = (const float4*)(e + (size_t)c0 * D);
                const float4* e1 = (const float4*)(e + (size_t)c1 * D);
                float4 a0 = e0[lane], b0 = e0[lane + 32];
                float4 a1 = e1[lane], b1 = e1[lane + 32];
                float d0 = a0.x*za.x + a0.y*za.y + a0.z*za.z + a0.w*za.w
                         + b0.x*zc.x + b0.y*zc.y + b0.z*zc.z + b0.w*zc.w;
                float d1 = a1.x*za.x + a1.y*za.y + a1.z*za.z + a1.w*za.w
                         + b1.x*zc.x + b1.y*zc.y + b1.z*zc.z + b1.w*zc.w;
                #pragma unroll
                for (int o = 16; o > 0; o >>= 1) {
                    d0 += __shfl_xor_sync(0xffffffffu, d0, o);
                    d1 += __shfl_xor_sync(0xffffffffu, d1, o);
                }
                float s0 = g_e_half[c0] - d0;
                float s1 = g_e_half[c1] - d1;
                if (s0 < bm) { bm = s0; bi = c0; }
                if (s1 < bm) { bm = s1; bi = c1; }
            }
            if (lane == 0) { rbv[w] = bm; rbi[w] = bi; }
            __syncthreads();
            if (tid == 0) {
                float bv = rbv[0]; int bb = rbi[0];
                #pragma unroll
                for (int j = 1; j < 8; ++j)
                    if (rbv[j] < bv || (rbv[j] == bv && rbi[j] < bb)) { bv = rbv[j]; bb = rbi[j]; }
                s_best = bb;
                atomicAdd(&g_counts[bb], 1.0f);
            }
        }
        __syncthreads();
        int best = s_best;
        float q  = e[(size_t)best * D + tid];
        float dv = q - zs[tid];
        outq[(size_t)row * D + tid] = q;
        red[tid] = dv * dv;
        __syncthreads();
        for (int o = 128; o > 32; o >>= 1) {
            if (tid < o) red[tid] += red[tid + o];
            __syncthreads();
        }
        if (tid < 32) {
            float v = red[tid] + red[tid + 32];
            #pragma unroll
            for (int o = 16; o > 0; o >>= 1) v += __shfl_down_sync(0xffffffffu, v, o);
            if (tid == 0) atomicAdd(&g_loss, (double)v);
        }
        __syncthreads();
    }
}

__global__ void finalize_kernel(float* __restrict__ out, int N) {
    __shared__ float red[1024];
    int t = threadIdx.x;
    float p = g_counts[t] * (1.0f / (float)N);
    red[t] = p * logf(p + 1e-10f);
    __syncthreads();
    for (int o = 512; o > 0; o >>= 1) {
        if (t < o) red[t] += red[t + o];
        __syncthreads();
    }
    if (t == 0) {
        out[0] = 0.25f * (float)(g_loss / ((double)N * (double)D));
        out[(size_t)N * D + 1] = expf(-red[0]);
    }
}

// ---------------------------------------------------------------------------
extern "C" void kernel_launch(void* const* d_in, const int* in_sizes, int n_in,
                              void* d_out, int out_size) {
    const float* z = (const float*)d_in[0];   // z_e  [N, 256]
    const float* e = (const float*)d_in[1];   // emb  [1024, 256]
    float* out = (float*)d_out;               // [loss, quantized(N*256), perplexity]
    int N = in_sizes[0] / D;                  // 131072

    cudaFuncSetAttribute(vq_main, cudaFuncAttributeMaxDynamicSharedMemorySize, DYN_SMEM);

    // two no-op launches so vq_main stays at absolute launch index 3 (ncu window)
    noop_kernel<<<1, 32>>>();
    noop_kernel<<<1, 32>>>();
    prep_kernel<<<(KCODES * 32) / 256, 256>>>(e);
    vq_main<<<N / BM, 256, DYN_SMEM>>>(z, e, out + 1);
    rescue_kernel<<<1024, 256>>>(z, e, out + 1);
    finalize_kernel<<<1, 1024>>>(out, N);
}

// round 11
// speedup vs baseline: 1.0096x; 1.0096x over previous
#include <cuda_runtime.h>
#include <cuda_fp16.h>
#include <cstdint>

#define D        256
#define KCODES   1024
#define BM       128
#define THETA    0.08f
#define DYN_SMEM 149504

// ---- device scratch (no allocations allowed) ----
__device__ uint32_t g_epack[KCODES * 128];   // per code: 256 fp16 (512B row)
__device__ float    g_e_half[KCODES];
__device__ float    g_counts[KCODES];
__device__ int      g_flag_rows[131072];     // row | (full<<30)
__device__ int      g_flag_pair[131072];     // i1 | (i2<<16)
__device__ int      g_flag_cnt;
__device__ double   g_loss;

// ============================ helpers ============================
__device__ __forceinline__ uint32_t smem_u32(const void* p) {
    uint32_t a;
    asm("{ .reg .u64 t; cvta.to.shared.u64 t, %1; cvt.u32.u64 %0, t; }" : "=r"(a) : "l"(p));
    return a;
}

__device__ __forceinline__ void ldsm_x4(uint32_t& r0, uint32_t& r1, uint32_t& r2, uint32_t& r3,
                                        uint32_t addr) {
    asm volatile("ldmatrix.sync.aligned.m8n8.x4.shared.b16 {%0,%1,%2,%3}, [%4];"
                 : "=r"(r0), "=r"(r1), "=r"(r2), "=r"(r3) : "r"(addr));
}

__device__ __forceinline__ void mma_f16(float* c, const uint32_t* a, uint32_t b0, uint32_t b1) {
    asm volatile("mma.sync.aligned.m16n8k16.row.col.f32.f16.f16.f32 "
                 "{%0,%1,%2,%3}, {%4,%5,%6,%7}, {%8,%9}, {%0,%1,%2,%3};"
                 : "+f"(c[0]), "+f"(c[1]), "+f"(c[2]), "+f"(c[3])
                 : "r"(a[0]), "r"(a[1]), "r"(a[2]), "r"(a[3]), "r"(b0), "r"(b1));
}

#define CP_ASYNC16(dst, src) \
    asm volatile("cp.async.cg.shared.global [%0], [%1], 16;" :: "r"(dst), "l"(src) : "memory")
#define CP_COMMIT() asm volatile("cp.async.commit_group;" ::: "memory")
#define CP_WAIT_ALL() asm volatile("cp.async.wait_group 0;" ::: "memory")
#define BAR_GRP(id) asm volatile("bar.sync %0, 256;" :: "r"(id) : "memory")

// merge two top-3 lists (indices kept for top-2); ties prefer lower index
__device__ __forceinline__ void merge3(float& m1, int& i1, float& m2, int& i2, float& m3,
                                       float b1, int j1, float b2, int j2, float b3) {
    float n1, n2, n3; int k1, k2;
    if (b1 < m1 || (b1 == m1 && j1 < i1)) {
        n1 = b1; k1 = j1;
        if (m1 < b2 || (m1 == b2 && i1 < j2)) { n2 = m1; k2 = i1; n3 = fminf(b2, m2); }
        else                                   { n2 = b2; k2 = j2; n3 = fminf(m1, b3); }
    } else {
        n1 = m1; k1 = i1;
        if (b1 < m2 || (b1 == m2 && j1 < i2)) { n2 = b1; k2 = j1; n3 = fminf(m2, b2); }
        else                                   { n2 = m2; k2 = i2; n3 = fminf(b1, m3); }
    }
    m1 = n1; i1 = k1; m2 = n2; i2 = k2; m3 = n3;
}

#define UPD3(sl, sval, scol) do { \
    float _s = (sval); \
    if (_s < M1[sl])      { M3[sl] = M2[sl]; M2[sl] = M1[sl]; I2[sl] = I1[sl]; M1[sl] = _s; I1[sl] = (scol); } \
    else if (_s < M2[sl]) { M3[sl] = M2[sl]; M2[sl] = _s; I2[sl] = (scol); } \
    else if (_s < M3[sl]) { M3[sl] = _s; } \
} while (0)

// ============================ kernels ============================
__global__ void noop_kernel() {}

// One warp per code: pack 256 fp16 + 0.5*||e||^2 ; also reset globals
__global__ void prep_kernel(const float* __restrict__ e) {
    int tid  = threadIdx.x;
    int gw   = (blockIdx.x * blockDim.x + tid) >> 5;
    int lane = tid & 31;
    if (blockIdx.x < 4) g_counts[blockIdx.x * 256 + tid] = 0.0f;
    if (blockIdx.x == 0 && tid == 0) { g_loss = 0.0; g_flag_cnt = 0; }
    if (gw >= KCODES) return;
    const float4* er = (const float4*)(e + (size_t)gw * D);
    float4 a = er[lane * 2];
    float4 b = er[lane * 2 + 1];
    __half2 h0 = __floats2half2_rn(a.x, a.y);
    __half2 h1 = __floats2half2_rn(a.z, a.w);
    __half2 h2 = __floats2half2_rn(b.x, b.y);
    __half2 h3 = __floats2half2_rn(b.z, b.w);
    uint4 u;
    u.x = *(uint32_t*)&h0; u.y = *(uint32_t*)&h1;
    u.z = *(uint32_t*)&h2; u.w = *(uint32_t*)&h3;
    *(uint4*)&g_epack[gw * 128 + lane * 4] = u;
    float s = a.x*a.x + a.y*a.y + a.z*a.z + a.w*a.w
            + b.x*b.x + b.y*b.y + b.z*b.z + b.w*b.w;
    #pragma unroll
    for (int o = 16; o > 0; o >>= 1) s += __shfl_down_sync(0xffffffffu, s, o);
    if (lane == 0) g_e_half[gw] = 0.5f * s;
}

// load one B chunk (128 codes x 128B k-slice = 16KB) with XOR swizzle, by 256 threads
__device__ __forceinline__ void load_chunk(uint32_t dstb, int nt, int c, int gtid) {
    const char* src0 = (const char*)g_epack + (size_t)nt * 65536 + (size_t)c * 128;
    #pragma unroll
    for (int it = 0; it < 4; ++it) {
        int i = it * 256 + gtid;          // 1024 16B units
        int r = i >> 3, s = i & 7;
        uint32_t ps = (uint32_t)s ^ ((uint32_t)r & 7u);
        CP_ASYNC16(dstb + (uint32_t)r * 128u + ps * 16u, src0 + (size_t)r * 512 + s * 16);
    }
    CP_COMMIT();
}

__global__ __launch_bounds__(512, 1) void vq_main(const float* __restrict__ z,
                                                  const float* __restrict__ e,
                                                  float* __restrict__ outq) {
    extern __shared__ char dsm[];
    char* base = (char*)(((uintptr_t)dsm + 1023) & ~(uintptr_t)1023);
    char*  sA   = base;                       // 65536 : 128 rows x 256 fp16 (swizzled, 512B rows)
    char*  sB   = base + 65536;               // 4 x 16384 (2 per group)
    float* s_eh = (float*)(base + 131072);    // 1024 f
    float* rm1  = (float*)(base + 135168);    // 128 x 4
    float* rm2  = (float*)(base + 137216);
    float* rm3  = (float*)(base + 139264);
    int*   ri1  = (int*)  (base + 141312);
    int*   ri2  = (int*)  (base + 143360);
    int*   sidx = (int*)  (base + 145408);    // 128
    int*   sflg = (int*)  (base + 145920);    // 128
    float* red  = (float*)(base + 146432);    // 512 f

    const int tid  = threadIdx.x;
    const int lane = tid & 31;
    const int w    = tid >> 5;
    const int grp  = w >> 3;        // 0/1 : independent pipeline
    const int gtid = tid & 255;
    const int wm   = (w & 7) >> 1;  // 0..3 : M warp (32 rows)
    const int wn   = w & 1;         // 0..1 : N warp (64 cols)
    const int rowbase = blockIdx.x * BM;
    const uint32_t sAu = smem_u32(sA);
    const uint32_t gbuf = smem_u32(sB) + (uint32_t)grp * 32768u;

    // prologue: first two chunks of this group (nt=grp, c=0 and c=1)
    load_chunk(gbuf,          grp, 0, gtid);
    load_chunk(gbuf + 16384u, grp, 1, gtid);

    for (int i = tid; i < KCODES; i += 512) s_eh[i] = g_e_half[i];

    // ---- convert this CTA's 128 z rows into swizzled fp16 SMEM A ----
    const float4* zb = (const float4*)(z + (size_t)rowbase * D);
    #pragma unroll
    for (int i = 0; i < 16; ++i) {
        int idx = i * 512 + tid;           // 8192 float4s
        int r = idx >> 6, f = idx & 63;
        float4 v = zb[r * 64 + f];
        __half2 p0 = __floats2half2_rn(v.x, v.y);
        __half2 p1 = __floats2half2_rn(v.z, v.w);
        uint2 u; u.x = *(uint32_t*)&p0; u.y = *(uint32_t*)&p1;
        uint32_t seg = (uint32_t)(f >> 1);
        uint32_t ps = (seg & ~7u) | ((seg & 7u) ^ ((uint32_t)r & 7u));
        *(uint2*)(sA + (size_t)r * 512 + ps * 16 + (f & 1) * 8) = u;
    }
    __syncthreads();   // sA + s_eh visible to both groups

    const float INF = __int_as_float(0x7f800000);
    float M1[4], M2[4], M3[4];
    int   I1[4], I2[4];
    #pragma unroll
    for (int s = 0; s < 4; ++s) { M1[s] = INF; M2[s] = INF; M3[s] = INF; I1[s] = 0; I2[s] = 0; }

    float acc[2][4][2][4];

    // ---- per-group pipeline: 16 chunks (4 nt x 4 k-slices) ----
    #pragma unroll 1
    for (int k = 0; k < 16; ++k) {
        int c = k & 3;
        if (c == 0) {
            #pragma unroll
            for (int a = 0; a < 2; ++a)
                #pragma unroll
                for (int p = 0; p < 4; ++p)
                    #pragma unroll
                    for (int q = 0; q < 2; ++q)
                        #pragma unroll
                        for (int x = 0; x < 4; ++x) acc[a][p][q][x] = 0.0f;
        }
        CP_WAIT_ALL();
        BAR_GRP(grp + 1);       // chunk k visible to group; buf((k+1)&1) free
        if (k >= 1 && k + 1 < 16) {
            int kn = k + 1;
            load_chunk(gbuf + (uint32_t)(kn & 1) * 16384u,
                       2 * (kn >> 2) + grp, kn & 3, gtid);
        }

        uint32_t bufo = (uint32_t)(k & 1) * 16384u;

        #pragma unroll
        for (int ks = 0; ks < 4; ++ks) {
            // A fragments (reused across all 4 p-groups)
            uint32_t afr0[4], afr1[4];
            {
                uint32_t seg = (uint32_t)(c * 8 + ks * 2) + (uint32_t)(lane >> 4);
                int ar0 = wm * 32 + (lane & 15);
                int ar1 = ar0 + 16;
                uint32_t ps0 = (seg & ~7u) | ((seg & 7u) ^ ((uint32_t)ar0 & 7u));
                uint32_t ps1 = (seg & ~7u) | ((seg & 7u) ^ ((uint32_t)ar1 & 7u));
                ldsm_x4(afr0[0], afr0[1], afr0[2], afr0[3],
                        sAu + (uint32_t)ar0 * 512u + ps0 * 16u);
                ldsm_x4(afr1[0], afr1[1], afr1[2], afr1[3],
                        sAu + (uint32_t)ar1 * 512u + ps1 * 16u);
            }
            // B fragments consumed immediately (low register pressure)
            #pragma unroll
            for (int p = 0; p < 4; ++p) {
                int br = wn * 64 + p * 16 + (lane & 7) + ((lane >> 4) & 1) * 8;
                uint32_t ls = (uint32_t)(ks * 2) + (uint32_t)((lane >> 3) & 1);
                uint32_t ps = ls ^ ((uint32_t)br & 7u);
                uint32_t b0, b1, b2, b3;
                ldsm_x4(b0, b1, b2, b3, gbuf + bufo + (uint32_t)br * 128u + ps * 16u);
                mma_f16(acc[0][p][0], afr0, b0, b1);
                mma_f16(acc[0][p][1], afr0, b2, b3);
                mma_f16(acc[1][p][0], afr1, b0, b1);
                mma_f16(acc[1][p][1], afr1, b2, b3);
            }
        }

        if (c == 3) {
            int nt = 2 * (k >> 2) + grp;
            int ntb = nt * 128 + wn * 64;
            #pragma unroll
            for (int mf = 0; mf < 2; ++mf)
                #pragma unroll
                for (int p = 0; p < 4; ++p)
                    #pragma unroll
                    for (int q = 0; q < 2; ++q) {
                        int colb = ntb + p * 16 + q * 8 + (lane & 3) * 2;
                        float e0 = s_eh[colb], e1 = s_eh[colb + 1];
                        UPD3(mf * 2 + 0, e0 - acc[mf][p][q][0], colb);
                        UPD3(mf * 2 + 0, e1 - acc[mf][p][q][1], colb + 1);
                        UPD3(mf * 2 + 1, e0 - acc[mf][p][q][2], colb);
                        UPD3(mf * 2 + 1, e1 - acc[mf][p][q][3], colb + 1);
                    }
        }
    }

    // ---- reduce across the 4 lanes sharing each row ----
    #pragma unroll
    for (int sl = 0; sl < 4; ++sl) {
        float m1 = M1[sl], m2 = M2[sl], m3 = M3[sl];
        int i1 = I1[sl], i2 = I2[sl];
        #pragma unroll
        for (int o = 1; o <= 2; o <<= 1) {
            float b1 = __shfl_xor_sync(0xffffffffu, m1, o);
            float b2 = __shfl_xor_sync(0xffffffffu, m2, o);
            float b3 = __shfl_xor_sync(0xffffffffu, m3, o);
            int   j1 = __shfl_xor_sync(0xffffffffu, i1, o);
            int   j2 = __shfl_xor_sync(0xffffffffu, i2, o);
            merge3(m1, i1, m2, i2, m3, b1, j1, b2, j2, b3);
        }
        if ((lane & 3) == 0) {
            int row = wm * 32 + (sl >> 1) * 16 + (sl & 1) * 8 + (lane >> 2);
            int ent = row * 4 + grp * 2 + wn;
            rm1[ent] = m1; rm2[ent] = m2; rm3[ent] = m3;
            ri1[ent] = i1; ri2[ent] = i2;
        }
    }
    __syncthreads();

    if (tid < BM) {
        float m1 = rm1[tid * 4], m2 = rm2[tid * 4], m3 = rm3[tid * 4];
        int   i1 = ri1[tid * 4], i2 = ri2[tid * 4];
        #pragma unroll
        for (int t = 1; t < 4; ++t)
            merge3(m1, i1, m2, i2, m3,
                   rm1[tid * 4 + t], ri1[tid * 4 + t],
                   rm2[tid * 4 + t], ri2[tid * 4 + t], rm3[tid * 4 + t]);
        int pairf = (m2 - m1 < THETA) ? 1 : 0;
        int fullf = (m3 - m1 < THETA) ? 1 : 0;
        sidx[tid] = i1;
        sflg[tid] = pairf;
        if (pairf) {
            int p = atomicAdd(&g_flag_cnt, 1);
            g_flag_rows[p] = (rowbase + tid) | (fullf << 30);
            g_flag_pair[p] = i1 | (i2 << 16);
        } else {
            atomicAdd(&g_counts[i1], 1.0f);
        }
    }
    __syncthreads();

    // ---- fused output: gather + loss for non-flagged rows ----
    float lacc = 0.0f;
    #pragma unroll 4
    for (int p = tid; p < BM * D; p += 512) {
        int r = p >> 8;
        int cc = p & 255;
        if (!sflg[r]) {
            float q  = e[(size_t)sidx[r] * D + cc];
            float zv = z[(size_t)(rowbase + r) * D + cc];
            outq[(size_t)(rowbase + r) * D + cc] = q;
            float d = q - zv;
            lacc += d * d;
        }
    }
    red[tid] = lacc;
    __syncthreads();
    for (int o = 256; o > 32; o >>= 1) {
        if (tid < o) red[tid] += red[tid + o];
        __syncthreads();
    }
    if (tid < 32) {
        float v = red[tid] + red[tid + 32];
        #pragma unroll
        for (int o = 16; o > 0; o >>= 1) v += __shfl_down_sync(0xffffffffu, v, o);
        if (tid == 0) atomicAdd(&g_loss, (double)v);
    }
}

// exact fp32 rescue, WARP-PER-ROW: pair-compare (common) or full rescan (rare),
// then write the output row + loss + count.
__global__ __launch_bounds__(256) void rescue_kernel(const float* __restrict__ z,
                                                     const float* __restrict__ e,
                                                     float* __restrict__ outq) {
    int cnt  = g_flag_cnt;
    int lane = threadIdx.x & 31;
    int gw   = blockIdx.x * 8 + (threadIdx.x >> 5);
    int nw   = gridDim.x * 8;
    for (int ri = gw; ri < cnt; ri += nw) {
        int rowp = g_flag_rows[ri];
        int row  = rowp & 0x3fffffff;
        int full = (rowp >> 30) & 1;
        int pair = g_flag_pair[ri];
        const float4* zr = (const float4*)(z + (size_t)row * D);
        float4 za = zr[lane];
        float4 zc = zr[lane + 32];

        int best;
        if (!full) {
            int c0 = pair & 0xffff, c1 = pair >> 16;
            const float4* e0 = (const float4*)(e + (size_t)c0 * D);
            const float4* e1 = (const float4*)(e + (size_t)c1 * D);
            float4 a0 = e0[lane], b0 = e0[lane + 32];
            float4 a1 = e1[lane], b1 = e1[lane + 32];
            float d0 = a0.x*za.x + a0.y*za.y + a0.z*za.z + a0.w*za.w
                     + b0.x*zc.x + b0.y*zc.y + b0.z*zc.z + b0.w*zc.w;
            float d1 = a1.x*za.x + a1.y*za.y + a1.z*za.z + a1.w*za.w
                     + b1.x*zc.x + b1.y*zc.y + b1.z*zc.z + b1.w*zc.w;
            #pragma unroll
            for (int o = 16; o > 0; o >>= 1) {
                d0 += __shfl_xor_sync(0xffffffffu, d0, o);
                d1 += __shfl_xor_sync(0xffffffffu, d1, o);
            }
            float s0 = g_e_half[c0] - d0;
            float s1 = g_e_half[c1] - d1;
            best = (s1 < s0 || (s1 == s0 && c1 < c0)) ? c1 : c0;
        } else {
            float bm = __int_as_float(0x7f800000);
            int   bi = KCODES;
            #pragma unroll 1
            for (int k = 0; k < KCODES; k += 2) {
                const float4* e0 = (const float4*)(e + (size_t)k * D);
                const float4* e1 = (const float4*)(e + (size_t)(k + 1) * D);
                float4 a0 = e0[lane], b0 = e0[lane + 32];
                float4 a1 = e1[lane], b1 = e1[lane + 32];
                float d0 = a0.x*za.x + a0.y*za.y + a0.z*za.z + a0.w*za.w
                         + b0.x*zc.x + b0.y*zc.y + b0.z*zc.z + b0.w*zc.w;
                float d1 = a1.x*za.x + a1.y*za.y + a1.z*za.z + a1.w*za.w
                         + b1.x*zc.x + b1.y*zc.y + b1.z*zc.z + b1.w*zc.w;
                #pragma unroll
                for (int o = 16; o > 0; o >>= 1) {
                    d0 += __shfl_xor_sync(0xffffffffu, d0, o);
                    d1 += __shfl_xor_sync(0xffffffffu, d1, o);
                }
                float s0 = g_e_half[k] - d0;
                float s1 = g_e_half[k + 1] - d1;
                if (s0 < bm) { bm = s0; bi = k; }
                if (s1 < bm) { bm = s1; bi = k + 1; }
            }
            best = bi;
        }

        if (lane == 0) atomicAdd(&g_counts[best], 1.0f);

        // output row + loss (coalesced 32-wide segments)
        const float* er = e + (size_t)best * D;
        const float* zrow = z + (size_t)row * D;
        float* orow = outq + (size_t)row * D;
        float ls = 0.0f;
        #pragma unroll
        for (int j = 0; j < 8; ++j) {
            int idx = lane + 32 * j;
            float q  = er[idx];
            float dv = q - zrow[idx];
            orow[idx] = q;
            ls += dv * dv;
        }
        #pragma unroll
        for (int o = 16; o > 0; o >>= 1) ls += __shfl_xor_sync(0xffffffffu, ls, o);
        if (lane == 0) atomicAdd(&g_loss, (double)ls);
    }
}

__global__ void finalize_kernel(float* __restrict__ out, int N) {
    __shared__ float red[1024];
    int t = threadIdx.x;
    float p = g_counts[t] * (1.0f / (float)N);
    red[t] = p * logf(p + 1e-10f);
    __syncthreads();
    for (int o = 512; o > 0; o >>= 1) {
        if (t < o) red[t] += red[t + o];
        __syncthreads();
    }
    if (t == 0) {
        out[0] = 0.25f * (float)(g_loss / ((double)N * (double)D));
        out[(size_t)N * D + 1] = expf(-red[0]);
    }
}

// ---------------------------------------------------------------------------
extern "C" void kernel_launch(void* const* d_in, const int* in_sizes, int n_in,
                              void* d_out, int out_size) {
    const float* z = (const float*)d_in[0];   // z_e  [N, 256]
    const float* e = (const float*)d_in[1];   // emb  [1024, 256]
    float* out = (float*)d_out;               // [loss, quantized(N*256), perplexity]
    int N = in_sizes[0] / D;                  // 131072

    cudaFuncSetAttribute(vq_main, cudaFuncAttributeMaxDynamicSharedMemorySize, DYN_SMEM);

    // two no-op launches so vq_main stays at absolute launch index 3 (ncu window)
    noop_kernel<<<1, 32>>>();
    noop_kernel<<<1, 32>>>();
    prep_kernel<<<(KCODES * 32) / 256, 256>>>(e);
    vq_main<<<N / BM, 512, DYN_SMEM>>>(z, e, out + 1);
    rescue_kernel<<<1024, 256>>>(z, e, out + 1);
    finalize_kernel<<<1, 1024>>>(out, N);
}

// round 12
// speedup vs baseline: 1.5686x; 1.5536x over previous
#include <cuda_runtime.h>
#include <cuda_fp16.h>
#include <cstdint>

#define D        256
#define KCODES   1024
#define BM       128
#define THETA    0.08f
#define DYN_SMEM 149504

// ---- device scratch (no allocations allowed) ----
__device__ uint32_t g_epack[KCODES * 128];   // per code: 256 fp16 (512B row)
__device__ float    g_e_half[KCODES];
__device__ float    g_counts[KCODES];
__device__ int      g_flag_rows[131072];     // rows needing full fp32 rescan
__device__ int      g_flag_cnt;
__device__ double   g_loss;

// ============================ helpers ============================
__device__ __forceinline__ uint32_t smem_u32(const void* p) {
    uint32_t a;
    asm("{ .reg .u64 t; cvta.to.shared.u64 t, %1; cvt.u32.u64 %0, t; }" : "=r"(a) : "l"(p));
    return a;
}

__device__ __forceinline__ void ldsm_x4(uint32_t& r0, uint32_t& r1, uint32_t& r2, uint32_t& r3,
                                        uint32_t addr) {
    asm volatile("ldmatrix.sync.aligned.m8n8.x4.shared.b16 {%0,%1,%2,%3}, [%4];"
                 : "=r"(r0), "=r"(r1), "=r"(r2), "=r"(r3) : "r"(addr));
}

__device__ __forceinline__ void mma_f16(float* c, const uint32_t* a, uint32_t b0, uint32_t b1) {
    asm volatile("mma.sync.aligned.m16n8k16.row.col.f32.f16.f16.f32 "
                 "{%0,%1,%2,%3}, {%4,%5,%6,%7}, {%8,%9}, {%0,%1,%2,%3};"
                 : "+f"(c[0]), "+f"(c[1]), "+f"(c[2]), "+f"(c[3])
                 : "r"(a[0]), "r"(a[1]), "r"(a[2]), "r"(a[3]), "r"(b0), "r"(b1));
}

#define CP_ASYNC16(dst, src) \
    asm volatile("cp.async.cg.shared.global [%0], [%1], 16;" :: "r"(dst), "l"(src) : "memory")
#define CP_COMMIT() asm volatile("cp.async.commit_group;" ::: "memory")
#define CP_WAIT_ALL() asm volatile("cp.async.wait_group 0;" ::: "memory")
#define BAR_GRP(id) asm volatile("bar.sync %0, 256;" :: "r"(id) : "memory")

// merge two top-3 lists (indices kept for top-2); ties prefer lower index
__device__ __forceinline__ void merge3(float& m1, int& i1, float& m2, int& i2, float& m3,
                                       float b1, int j1, float b2, int j2, float b3) {
    float n1, n2, n3; int k1, k2;
    if (b1 < m1 || (b1 == m1 && j1 < i1)) {
        n1 = b1; k1 = j1;
        if (m1 < b2 || (m1 == b2 && i1 < j2)) { n2 = m1; k2 = i1; n3 = fminf(b2, m2); }
        else                                   { n2 = b2; k2 = j2; n3 = fminf(m1, b3); }
    } else {
        n1 = m1; k1 = i1;
        if (b1 < m2 || (b1 == m2 && j1 < i2)) { n2 = b1; k2 = j1; n3 = fminf(m2, b2); }
        else                                   { n2 = m2; k2 = i2; n3 = fminf(b1, m3); }
    }
    m1 = n1; i1 = k1; m2 = n2; i2 = k2; m3 = n3;
}

#define UPD3(sl, sval, scol) do { \
    float _s = (sval); \
    if (_s < M1[sl])      { M3[sl] = M2[sl]; M2[sl] = M1[sl]; I2[sl] = I1[sl]; M1[sl] = _s; I1[sl] = (scol); } \
    else if (_s < M2[sl]) { M3[sl] = M2[sl]; M2[sl] = _s; I2[sl] = (scol); } \
    else if (_s < M3[sl]) { M3[sl] = _s; } \
} while (0)

// ============================ kernels ============================
__global__ void noop_kernel() {}

// One warp per code: pack 256 fp16 + 0.5*||e||^2 ; also reset globals
__global__ void prep_kernel(const float* __restrict__ e) {
    int tid  = threadIdx.x;
    int gw   = (blockIdx.x * blockDim.x + tid) >> 5;
    int lane = tid & 31;
    if (blockIdx.x < 4) g_counts[blockIdx.x * 256 + tid] = 0.0f;
    if (blockIdx.x == 0 && tid == 0) { g_loss = 0.0; g_flag_cnt = 0; }
    if (gw >= KCODES) return;
    const float4* er = (const float4*)(e + (size_t)gw * D);
    float4 a = er[lane * 2];
    float4 b = er[lane * 2 + 1];
    __half2 h0 = __floats2half2_rn(a.x, a.y);
    __half2 h1 = __floats2half2_rn(a.z, a.w);
    __half2 h2 = __floats2half2_rn(b.x, b.y);
    __half2 h3 = __floats2half2_rn(b.z, b.w);
    uint4 u;
    u.x = *(uint32_t*)&h0; u.y = *(uint32_t*)&h1;
    u.z = *(uint32_t*)&h2; u.w = *(uint32_t*)&h3;
    *(uint4*)&g_epack[gw * 128 + lane * 4] = u;
    float s = a.x*a.x + a.y*a.y + a.z*a.z + a.w*a.w
            + b.x*b.x + b.y*b.y + b.z*b.z + b.w*b.w;
    #pragma unroll
    for (int o = 16; o > 0; o >>= 1) s += __shfl_down_sync(0xffffffffu, s, o);
    if (lane == 0) g_e_half[gw] = 0.5f * s;
}

// load one B chunk (128 codes x 128B k-slice = 16KB) with XOR swizzle, by 256 threads
__device__ __forceinline__ void load_chunk(uint32_t dstb, int nt, int c, int gtid) {
    const char* src0 = (const char*)g_epack + (size_t)nt * 65536 + (size_t)c * 128;
    #pragma unroll
    for (int it = 0; it < 4; ++it) {
        int i = it * 256 + gtid;          // 1024 16B units
        int r = i >> 3, s = i & 7;
        uint32_t ps = (uint32_t)s ^ ((uint32_t)r & 7u);
        CP_ASYNC16(dstb + (uint32_t)r * 128u + ps * 16u, src0 + (size_t)r * 512 + s * 16);
    }
    CP_COMMIT();
}

__global__ __launch_bounds__(512, 1) void vq_main(const float* __restrict__ z,
                                                  const float* __restrict__ e,
                                                  float* __restrict__ outq) {
    extern __shared__ char dsm[];
    char* base = (char*)(((uintptr_t)dsm + 1023) & ~(uintptr_t)1023);
    char*  sA    = base;                       // 65536 : 128 rows x 256 fp16 (swizzled)
    char*  sB    = base + 65536;               // 4 x 16384 (2 per group)
    float* s_eh  = (float*)(base + 131072);    // 1024 f
    float* rm1   = (float*)(base + 135168);    // 128 x 4
    float* rm2   = (float*)(base + 137216);
    float* rm3   = (float*)(base + 139264);
    int*   ri1   = (int*)  (base + 141312);
    int*   ri2   = (int*)  (base + 143360);
    int*   sidx  = (int*)  (base + 145408);    // 128
    int*   sflg  = (int*)  (base + 145920);    // 128 (full-rescan rows; excluded from output)
    float* red   = (float*)(base + 146432);    // 512 f
    int*   sp2   = (int*)  (base + 148480);    // 128 (second candidate)
    int*   spair = (int*)  (base + 148992);    // 128 (pair-resolve flag)

    const int tid  = threadIdx.x;
    const int lane = tid & 31;
    const int w    = tid >> 5;
    const int grp  = w >> 3;        // 0/1 : independent pipeline
    const int gtid = tid & 255;
    const int wm   = (w & 7) >> 1;  // 0..3 : M warp (32 rows)
    const int wn   = w & 1;         // 0..1 : N warp (64 cols)
    const int rowbase = blockIdx.x * BM;
    const uint32_t sAu = smem_u32(sA);
    const uint32_t gbuf = smem_u32(sB) + (uint32_t)grp * 32768u;

    // prologue: first two chunks of this group
    load_chunk(gbuf,          grp, 0, gtid);
    load_chunk(gbuf + 16384u, grp, 1, gtid);

    for (int i = tid; i < KCODES; i += 512) s_eh[i] = g_e_half[i];

    // ---- convert this CTA's 128 z rows into swizzled fp16 SMEM A ----
    const float4* zb = (const float4*)(z + (size_t)rowbase * D);
    #pragma unroll
    for (int i = 0; i < 16; ++i) {
        int idx = i * 512 + tid;           // 8192 float4s
        int r = idx >> 6, f = idx & 63;
        float4 v = zb[r * 64 + f];
        __half2 p0 = __floats2half2_rn(v.x, v.y);
        __half2 p1 = __floats2half2_rn(v.z, v.w);
        uint2 u; u.x = *(uint32_t*)&p0; u.y = *(uint32_t*)&p1;
        uint32_t seg = (uint32_t)(f >> 1);
        uint32_t ps = (seg & ~7u) | ((seg & 7u) ^ ((uint32_t)r & 7u));
        *(uint2*)(sA + (size_t)r * 512 + ps * 16 + (f & 1) * 8) = u;
    }
    __syncthreads();   // sA + s_eh visible to both groups

    const float INF = __int_as_float(0x7f800000);
    float M1[4], M2[4], M3[4];
    int   I1[4], I2[4];
    #pragma unroll
    for (int s = 0; s < 4; ++s) { M1[s] = INF; M2[s] = INF; M3[s] = INF; I1[s] = 0; I2[s] = 0; }

    float acc[2][4][2][4];

    // ---- per-group pipeline: 16 chunks (4 nt x 4 k-slices) ----
    #pragma unroll 1
    for (int k = 0; k < 16; ++k) {
        int c = k & 3;
        if (c == 0) {
            #pragma unroll
            for (int a = 0; a < 2; ++a)
                #pragma unroll
                for (int p = 0; p < 4; ++p)
                    #pragma unroll
                    for (int q = 0; q < 2; ++q)
                        #pragma unroll
                        for (int x = 0; x < 4; ++x) acc[a][p][q][x] = 0.0f;
        }
        CP_WAIT_ALL();
        BAR_GRP(grp + 1);       // chunk k visible to group; buf((k+1)&1) free
        if (k >= 1 && k + 1 < 16) {
            int kn = k + 1;
            load_chunk(gbuf + (uint32_t)(kn & 1) * 16384u,
                       2 * (kn >> 2) + grp, kn & 3, gtid);
        }

        uint32_t bufo = (uint32_t)(k & 1) * 16384u;

        #pragma unroll
        for (int ks = 0; ks < 4; ++ks) {
            uint32_t afr0[4], afr1[4];
            {
                uint32_t seg = (uint32_t)(c * 8 + ks * 2) + (uint32_t)(lane >> 4);
                int ar0 = wm * 32 + (lane & 15);
                int ar1 = ar0 + 16;
                uint32_t ps0 = (seg & ~7u) | ((seg & 7u) ^ ((uint32_t)ar0 & 7u));
                uint32_t ps1 = (seg & ~7u) | ((seg & 7u) ^ ((uint32_t)ar1 & 7u));
                ldsm_x4(afr0[0], afr0[1], afr0[2], afr0[3],
                        sAu + (uint32_t)ar0 * 512u + ps0 * 16u);
                ldsm_x4(afr1[0], afr1[1], afr1[2], afr1[3],
                        sAu + (uint32_t)ar1 * 512u + ps1 * 16u);
            }
            #pragma unroll
            for (int p = 0; p < 4; ++p) {
                int br = wn * 64 + p * 16 + (lane & 7) + ((lane >> 4) & 1) * 8;
                uint32_t ls = (uint32_t)(ks * 2) + (uint32_t)((lane >> 3) & 1);
                uint32_t ps = ls ^ ((uint32_t)br & 7u);
                uint32_t b0, b1, b2, b3;
                ldsm_x4(b0, b1, b2, b3, gbuf + bufo + (uint32_t)br * 128u + ps * 16u);
                mma_f16(acc[0][p][0], afr0, b0, b1);
                mma_f16(acc[0][p][1], afr0, b2, b3);
                mma_f16(acc[1][p][0], afr1, b0, b1);
                mma_f16(acc[1][p][1], afr1, b2, b3);
            }
        }

        if (c == 3) {
            int nt = 2 * (k >> 2) + grp;
            int ntb = nt * 128 + wn * 64;
            #pragma unroll
            for (int mf = 0; mf < 2; ++mf)
                #pragma unroll
                for (int p = 0; p < 4; ++p)
                    #pragma unroll
                    for (int q = 0; q < 2; ++q) {
                        int colb = ntb + p * 16 + q * 8 + (lane & 3) * 2;
                        float e0 = s_eh[colb], e1 = s_eh[colb + 1];
                        UPD3(mf * 2 + 0, e0 - acc[mf][p][q][0], colb);
                        UPD3(mf * 2 + 0, e1 - acc[mf][p][q][1], colb + 1);
                        UPD3(mf * 2 + 1, e0 - acc[mf][p][q][2], colb);
                        UPD3(mf * 2 + 1, e1 - acc[mf][p][q][3], colb + 1);
                    }
        }
    }

    // ---- reduce across the 4 lanes sharing each row ----
    #pragma unroll
    for (int sl = 0; sl < 4; ++sl) {
        float m1 = M1[sl], m2 = M2[sl], m3 = M3[sl];
        int i1 = I1[sl], i2 = I2[sl];
        #pragma unroll
        for (int o = 1; o <= 2; o <<= 1) {
            float b1 = __shfl_xor_sync(0xffffffffu, m1, o);
            float b2 = __shfl_xor_sync(0xffffffffu, m2, o);
            float b3 = __shfl_xor_sync(0xffffffffu, m3, o);
            int   j1 = __shfl_xor_sync(0xffffffffu, i1, o);
            int   j2 = __shfl_xor_sync(0xffffffffu, i2, o);
            merge3(m1, i1, m2, i2, m3, b1, j1, b2, j2, b3);
        }
        if ((lane & 3) == 0) {
            int row = wm * 32 + (sl >> 1) * 16 + (sl & 1) * 8 + (lane >> 2);
            int ent = row * 4 + grp * 2 + wn;
            rm1[ent] = m1; rm2[ent] = m2; rm3[ent] = m3;
            ri1[ent] = i1; ri2[ent] = i2;
        }
    }
    __syncthreads();

    if (tid < BM) {
        float m1 = rm1[tid * 4], m2 = rm2[tid * 4], m3 = rm3[tid * 4];
        int   i1 = ri1[tid * 4], i2 = ri2[tid * 4];
        #pragma unroll
        for (int t = 1; t < 4; ++t)
            merge3(m1, i1, m2, i2, m3,
                   rm1[tid * 4 + t], ri1[tid * 4 + t],
                   rm2[tid * 4 + t], ri2[tid * 4 + t], rm3[tid * 4 + t]);
        int pairf = (m2 - m1 < THETA) ? 1 : 0;
        int fullf = (m3 - m1 < THETA) ? 1 : 0;
        sidx[tid]  = i1;
        sp2[tid]   = i2;
        spair[tid] = pairf && !fullf;
        sflg[tid]  = fullf;
        if (fullf) {
            int p = atomicAdd(&g_flag_cnt, 1);
            g_flag_rows[p] = rowbase + tid;
        } else if (!pairf) {
            atomicAdd(&g_counts[i1], 1.0f);
        }
    }
    __syncthreads();

    // ---- in-kernel pair resolve: warp-per-row exact fp32 compare {i1, i2} ----
    #pragma unroll 1
    for (int r = w; r < BM; r += 16) {
        if (!spair[r]) continue;
        const float4* zr = (const float4*)(z + (size_t)(rowbase + r) * D);
        float4 za = zr[lane];
        float4 zc = zr[lane + 32];
        int c0 = sidx[r], c1 = sp2[r];
        const float4* e0 = (const float4*)(e + (size_t)c0 * D);
        const float4* e1 = (const float4*)(e + (size_t)c1 * D);
        float4 a0 = e0[lane], b0 = e0[lane + 32];
        float4 a1 = e1[lane], b1 = e1[lane + 32];
        float d0 = a0.x*za.x + a0.y*za.y + a0.z*za.z + a0.w*za.w
                 + b0.x*zc.x + b0.y*zc.y + b0.z*zc.z + b0.w*zc.w;
        float d1 = a1.x*za.x + a1.y*za.y + a1.z*za.z + a1.w*za.w
                 + b1.x*zc.x + b1.y*zc.y + b1.z*zc.z + b1.w*zc.w;
        #pragma unroll
        for (int o = 16; o > 0; o >>= 1) {
            d0 += __shfl_xor_sync(0xffffffffu, d0, o);
            d1 += __shfl_xor_sync(0xffffffffu, d1, o);
        }
        if (lane == 0) {
            float s0 = s_eh[c0] - d0;
            float s1 = s_eh[c1] - d1;
            int best = (s1 < s0 || (s1 == s0 && c1 < c0)) ? c1 : c0;
            sidx[r] = best;
            atomicAdd(&g_counts[best], 1.0f);
        }
    }
    __syncthreads();

    // ---- fused output: gather + loss for all non-full rows ----
    float lacc = 0.0f;
    #pragma unroll 4
    for (int p = tid; p < BM * D; p += 512) {
        int r = p >> 8;
        int cc = p & 255;
        if (!sflg[r]) {
            float q  = e[(size_t)sidx[r] * D + cc];
            float zv = z[(size_t)(rowbase + r) * D + cc];
            outq[(size_t)(rowbase + r) * D + cc] = q;
            float d = q - zv;
            lacc += d * d;
        }
    }
    red[tid] = lacc;
    __syncthreads();
    for (int o = 256; o > 32; o >>= 1) {
        if (tid < o) red[tid] += red[tid + o];
        __syncthreads();
    }
    if (tid < 32) {
        float v = red[tid] + red[tid + 32];
        #pragma unroll
        for (int o = 16; o > 0; o >>= 1) v += __shfl_down_sync(0xffffffffu, v, o);
        if (tid == 0) atomicAdd(&g_loss, (double)v);
    }
}

// full exact fp32 rescan, BLOCK-per-row (8 warps x 128 codes, ILP2); rare rows only
__global__ __launch_bounds__(256) void rescue_full(const float* __restrict__ z,
                                                   const float* __restrict__ e,
                                                   float* __restrict__ outq) {
    __shared__ float zs[256];
    __shared__ float rbv[8];
    __shared__ int   rbi[8];
    __shared__ int   s_best;
    __shared__ float red[256];
    int cnt = g_flag_cnt;
    int tid = threadIdx.x, w = tid >> 5, lane = tid & 31;
    for (int ri = blockIdx.x; ri < cnt; ri += gridDim.x) {
        int row = g_flag_rows[ri];
        if (tid < 64) ((float4*)zs)[tid] = ((const float4*)(z + (size_t)row * D))[tid];
        __syncthreads();
        float4 za = ((const float4*)zs)[lane];
        float4 zc = ((const float4*)zs)[lane + 32];

        float bm = __int_as_float(0x7f800000);
        int   bi = KCODES;
        int wbase = w * 128;
        #pragma unroll 1
        for (int k = 0; k < 128; k += 2) {
            int c0 = wbase + k, c1 = c0 + 1;
            const float4* e0 = (const float4*)(e + (size_t)c0 * D);
            const float4* e1 = (const float4*)(e + (size_t)c1 * D);
            float4 a0 = e0[lane], b0 = e0[lane + 32];
            float4 a1 = e1[lane], b1 = e1[lane + 32];
            float d0 = a0.x*za.x + a0.y*za.y + a0.z*za.z + a0.w*za.w
                     + b0.x*zc.x + b0.y*zc.y + b0.z*zc.z + b0.w*zc.w;
            float d1 = a1.x*za.x + a1.y*za.y + a1.z*za.z + a1.w*za.w
                     + b1.x*zc.x + b1.y*zc.y + b1.z*zc.z + b1.w*zc.w;
            #pragma unroll
            for (int o = 16; o > 0; o >>= 1) {
                d0 += __shfl_xor_sync(0xffffffffu, d0, o);
                d1 += __shfl_xor_sync(0xffffffffu, d1, o);
            }
            float s0 = g_e_half[c0] - d0;
            float s1 = g_e_half[c1] - d1;
            if (s0 < bm) { bm = s0; bi = c0; }
            if (s1 < bm) { bm = s1; bi = c1; }
        }
        if (lane == 0) { rbv[w] = bm; rbi[w] = bi; }
        __syncthreads();
        if (tid == 0) {
            float bv = rbv[0]; int bb = rbi[0];
            #pragma unroll
            for (int j = 1; j < 8; ++j)
                if (rbv[j] < bv || (rbv[j] == bv && rbi[j] < bb)) { bv = rbv[j]; bb = rbi[j]; }
            s_best = bb;
            atomicAdd(&g_counts[bb], 1.0f);
        }
        __syncthreads();
        int best = s_best;
        float q  = e[(size_t)best * D + tid];
        float dv = q - zs[tid];
        outq[(size_t)row * D + tid] = q;
        red[tid] = dv * dv;
        __syncthreads();
        for (int o = 128; o > 32; o >>= 1) {
            if (tid < o) red[tid] += red[tid + o];
            __syncthreads();
        }
        if (tid < 32) {
            float v = red[tid] + red[tid + 32];
            #pragma unroll
            for (int o = 16; o > 0; o >>= 1) v += __shfl_down_sync(0xffffffffu, v, o);
            if (tid == 0) atomicAdd(&g_loss, (double)v);
        }
        __syncthreads();
    }
}

__global__ void finalize_kernel(float* __restrict__ out, int N) {
    __shared__ float red[1024];
    int t = threadIdx.x;
    float p = g_counts[t] * (1.0f / (float)N);
    red[t] = p * logf(p + 1e-10f);
    __syncthreads();
    for (int o = 512; o > 0; o >>= 1) {
        if (t < o) red[t] += red[t + o];
        __syncthreads();
    }
    if (t == 0) {
        out[0] = 0.25f * (float)(g_loss / ((double)N * (double)D));
        out[(size_t)N * D + 1] = expf(-red[0]);
    }
}

// ---------------------------------------------------------------------------
extern "C" void kernel_launch(void* const* d_in, const int* in_sizes, int n_in,
                              void* d_out, int out_size) {
    const float* z = (const float*)d_in[0];   // z_e  [N, 256]
    const float* e = (const float*)d_in[1];   // emb  [1024, 256]
    float* out = (float*)d_out;               // [loss, quantized(N*256), perplexity]
    int N = in_sizes[0] / D;                  // 131072

    cudaFuncSetAttribute(vq_main, cudaFuncAttributeMaxDynamicSharedMemorySize, DYN_SMEM);

    // two no-op launches so vq_main stays at absolute launch index 3 (ncu window)
    noop_kernel<<<1, 32>>>();
    noop_kernel<<<1, 32>>>();
    prep_kernel<<<(KCODES * 32) / 256, 256>>>(e);
    vq_main<<<N / BM, 512, DYN_SMEM>>>(z, e, out + 1);
    rescue_full<<<1024, 256>>>(z, e, out + 1);
    finalize_kernel<<<1, 1024>>>(out, N);
}

// round 13
// speedup vs baseline: 1.9960x; 1.2725x over previous
#include <cuda_runtime.h>
#include <cuda_fp16.h>
#include <cstdint>

#define D        256
#define KCODES   1024
#define BM       128
#define THETA_FIX 83886      // 0.08 * 2^20
#define DYN_SMEM 216064

// ---- device scratch (no allocations allowed) ----
__device__ uint32_t g_epack[KCODES * 128];   // per code: 256 fp16 (512B row)
__device__ float    g_e_half[KCODES];
__device__ float    g_counts[KCODES];
__device__ int      g_flag_rows[131072];     // rows needing full fp32 rescan
__device__ int      g_flag_cnt;
__device__ double   g_loss;

// ============================ helpers ============================
__device__ __forceinline__ uint32_t smem_u32(const void* p) {
    uint32_t a;
    asm("{ .reg .u64 t; cvta.to.shared.u64 t, %1; cvt.u32.u64 %0, t; }" : "=r"(a) : "l"(p));
    return a;
}

__device__ __forceinline__ void ldsm_x4(uint32_t& r0, uint32_t& r1, uint32_t& r2, uint32_t& r3,
                                        uint32_t addr) {
    asm volatile("ldmatrix.sync.aligned.m8n8.x4.shared.b16 {%0,%1,%2,%3}, [%4];"
                 : "=r"(r0), "=r"(r1), "=r"(r2), "=r"(r3) : "r"(addr));
}

__device__ __forceinline__ void mma_f16(float* c, const uint32_t* a, uint32_t b0, uint32_t b1) {
    asm volatile("mma.sync.aligned.m16n8k16.row.col.f32.f16.f16.f32 "
                 "{%0,%1,%2,%3}, {%4,%5,%6,%7}, {%8,%9}, {%0,%1,%2,%3};"
                 : "+f"(c[0]), "+f"(c[1]), "+f"(c[2]), "+f"(c[3])
                 : "r"(a[0]), "r"(a[1]), "r"(a[2]), "r"(a[3]), "r"(b0), "r"(b1));
}

#define CP_ASYNC16(dst, src) \
    asm volatile("cp.async.cg.shared.global [%0], [%1], 16;" :: "r"(dst), "l"(src) : "memory")
#define CP_COMMIT() asm volatile("cp.async.commit_group;" ::: "memory")
#define CP_WAIT2() asm volatile("cp.async.wait_group 2;" ::: "memory")
#define BAR_GRP(id) asm volatile("bar.sync %0, 256;" :: "r"(id) : "memory")

// branchless top-3 insert of packed int x (score*2^20 | col), sorted pm1<=pm2<=pm3
#define PACK3(sl, ehv, accv, col) do { \
    int _si = __float2int_rz(fmaf((accv), -1024.0f, (ehv))); \
    int _x  = _si * 1024 + (col); \
    pm3[sl] = min(pm3[sl], max(pm2[sl], _x)); \
    pm2[sl] = min(pm2[sl], max(pm1[sl], _x)); \
    pm1[sl] = min(pm1[sl], _x); \
} while (0)

// merge two sorted top-3 triples (8 min/max ops)
__device__ __forceinline__ void pmerge(int& a1, int& a2, int& a3, int b1, int b2, int b3) {
    int t1  = max(a1, b1);
    a1      = min(a1, b1);
    int m22 = min(a2, b2);
    int M22 = max(a2, b2);
    a2      = min(t1, m22);
    a3      = min(min(a3, b3), min(max(t1, m22), M22));
}

// ============================ kernels ============================
__global__ void noop_kernel() {}

// One warp per code: pack 256 fp16 + 0.5*||e||^2 ; also reset globals
__global__ void prep_kernel(const float* __restrict__ e) {
    int tid  = threadIdx.x;
    int gw   = (blockIdx.x * blockDim.x + tid) >> 5;
    int lane = tid & 31;
    if (blockIdx.x < 4) g_counts[blockIdx.x * 256 + tid] = 0.0f;
    if (blockIdx.x == 0 && tid == 0) { g_loss = 0.0; g_flag_cnt = 0; }
    if (gw >= KCODES) return;
    const float4* er = (const float4*)(e + (size_t)gw * D);
    float4 a = er[lane * 2];
    float4 b = er[lane * 2 + 1];
    __half2 h0 = __floats2half2_rn(a.x, a.y);
    __half2 h1 = __floats2half2_rn(a.z, a.w);
    __half2 h2 = __floats2half2_rn(b.x, b.y);
    __half2 h3 = __floats2half2_rn(b.z, b.w);
    uint4 u;
    u.x = *(uint32_t*)&h0; u.y = *(uint32_t*)&h1;
    u.z = *(uint32_t*)&h2; u.w = *(uint32_t*)&h3;
    *(uint4*)&g_epack[gw * 128 + lane * 4] = u;
    float s = a.x*a.x + a.y*a.y + a.z*a.z + a.w*a.w
            + b.x*b.x + b.y*b.y + b.z*b.z + b.w*b.w;
    #pragma unroll
    for (int o = 16; o > 0; o >>= 1) s += __shfl_down_sync(0xffffffffu, s, o);
    if (lane == 0) g_e_half[gw] = 0.5f * s;
}

// issue cp.asyncs for one B chunk (128 codes x 128B k-slice = 16KB), no commit
__device__ __forceinline__ void load_chunk_body(uint32_t dstb, int nt, int c, int gtid) {
    const char* src0 = (const char*)g_epack + (size_t)nt * 65536 + (size_t)c * 128;
    #pragma unroll
    for (int it = 0; it < 4; ++it) {
        int i = it * 256 + gtid;          // 1024 16B units
        int r = i >> 3, s = i & 7;
        uint32_t ps = (uint32_t)s ^ ((uint32_t)r & 7u);
        CP_ASYNC16(dstb + (uint32_t)r * 128u + ps * 16u, src0 + (size_t)r * 512 + s * 16);
    }
}

__global__ __launch_bounds__(512, 1) void vq_main(const float* __restrict__ z,
                                                  const float* __restrict__ e,
                                                  float* __restrict__ outq) {
    extern __shared__ char dsm[];
    char* base = (char*)(((uintptr_t)dsm + 1023) & ~(uintptr_t)1023);
    char*  sA      = base;                     // 65536 : 128 rows x 256 fp16 (swizzled)
    char*  sB      = base + 65536;             // 2 groups x 4 bufs x 16384
    float* s_eh    = (float*)(base + 196608);  // 1024 f  (exact 0.5||e||^2)
    float* s_eh1k  = (float*)(base + 200704);  // 1024 f  (x1024)
    int*   pm1s    = (int*)  (base + 204800);  // 128 x 4
    int*   pm2s    = (int*)  (base + 206848);
    int*   pm3s    = (int*)  (base + 208896);
    int*   sidx    = (int*)  (base + 210944);  // 128
    int*   sp2     = (int*)  (base + 211456);  // 128
    int*   spair   = (int*)  (base + 211968);  // 128
    int*   sflg    = (int*)  (base + 212480);  // 128
    float* red     = (float*)(base + 212992);  // 512 f

    const int tid  = threadIdx.x;
    const int lane = tid & 31;
    const int w    = tid >> 5;
    const int grp  = w >> 3;        // 0/1 : independent pipeline
    const int gtid = tid & 255;
    const int wm   = (w & 7) >> 1;  // 0..3 : M warp (32 rows)
    const int wn   = w & 1;         // 0..1 : N warp (64 cols)
    const int rowbase = blockIdx.x * BM;
    const uint32_t sAu = smem_u32(sA);
    const uint32_t gbuf = smem_u32(sB) + (uint32_t)grp * 65536u;

    // prologue: chunks 0,1,2 of this group (chunk k -> nt = 2*(k>>2)+grp, c = k&3, buf = k&3)
    load_chunk_body(gbuf,          grp, 0, gtid); CP_COMMIT();
    load_chunk_body(gbuf + 16384u, grp, 1, gtid); CP_COMMIT();
    load_chunk_body(gbuf + 32768u, grp, 2, gtid); CP_COMMIT();

    for (int i = tid; i < KCODES; i += 512) {
        float v = g_e_half[i];
        s_eh[i]   = v;
        s_eh1k[i] = v * 1024.0f;
    }

    // ---- convert this CTA's 128 z rows into swizzled fp16 SMEM A ----
    const float4* zb = (const float4*)(z + (size_t)rowbase * D);
    #pragma unroll
    for (int i = 0; i < 16; ++i) {
        int idx = i * 512 + tid;           // 8192 float4s
        int r = idx >> 6, f = idx & 63;
        float4 v = zb[r * 64 + f];
        __half2 p0 = __floats2half2_rn(v.x, v.y);
        __half2 p1 = __floats2half2_rn(v.z, v.w);
        uint2 u; u.x = *(uint32_t*)&p0; u.y = *(uint32_t*)&p1;
        uint32_t seg = (uint32_t)(f >> 1);
        uint32_t ps = (seg & ~7u) | ((seg & 7u) ^ ((uint32_t)r & 7u));
        *(uint2*)(sA + (size_t)r * 512 + ps * 16 + (f & 1) * 8) = u;
    }
    __syncthreads();   // sA + eh tables visible to both groups

    int pm1[4], pm2[4], pm3[4];
    #pragma unroll
    for (int s = 0; s < 4; ++s) { pm1[s] = 0x7FFFFFFF; pm2[s] = 0x7FFFFFFF; pm3[s] = 0x7FFFFFFF; }

    float acc[2][4][2][4];

    // ---- per-group pipeline: 16 chunks, 2-deep prefetch, c compile-time ----
    #pragma unroll 1
    for (int kc = 0; kc < 4; ++kc) {
        #pragma unroll
        for (int c4 = 0; c4 < 4; ++c4) {
            if (c4 == 0) {
                #pragma unroll
                for (int a = 0; a < 2; ++a)
                    #pragma unroll
                    for (int p = 0; p < 4; ++p)
                        #pragma unroll
                        for (int q = 0; q < 2; ++q)
                            #pragma unroll
                            for (int x = 0; x < 4; ++x) acc[a][p][q][x] = 0.0f;
            }
            CP_WAIT2();              // chunk k = kc*4+c4 arrived (always-commit keeps count)
            BAR_GRP(grp + 1);        // collective visibility; buf (k+3)&3 free for reuse
            {
                int kn = kc * 4 + c4 + 3;
                if (kn < 16)
                    load_chunk_body(gbuf + (uint32_t)((kn & 3) * 16384), 2 * (kn >> 2) + grp,
                                    kn & 3, gtid);
                CP_COMMIT();         // always commit (possibly empty group)
            }

            const uint32_t bufo = (uint32_t)(c4 * 16384);   // compile-time

            #pragma unroll
            for (int ks = 0; ks < 4; ++ks) {
                uint32_t afr0[4], afr1[4];
                {
                    uint32_t seg = (uint32_t)(c4 * 8 + ks * 2) + (uint32_t)(lane >> 4);
                    int ar0 = wm * 32 + (lane & 15);
                    int ar1 = ar0 + 16;
                    uint32_t ps0 = (seg & ~7u) | ((seg & 7u) ^ ((uint32_t)ar0 & 7u));
                    uint32_t ps1 = (seg & ~7u) | ((seg & 7u) ^ ((uint32_t)ar1 & 7u));
                    ldsm_x4(afr0[0], afr0[1], afr0[2], afr0[3],
                            sAu + (uint32_t)ar0 * 512u + ps0 * 16u);
                    ldsm_x4(afr1[0], afr1[1], afr1[2], afr1[3],
                            sAu + (uint32_t)ar1 * 512u + ps1 * 16u);
                }
                #pragma unroll
                for (int p = 0; p < 4; ++p) {
                    int br = wn * 64 + p * 16 + (lane & 7) + ((lane >> 4) & 1) * 8;
                    uint32_t ls = (uint32_t)(ks * 2) + (uint32_t)((lane >> 3) & 1);
                    uint32_t ps = ls ^ ((uint32_t)br & 7u);
                    uint32_t b0, b1, b2, b3;
                    ldsm_x4(b0, b1, b2, b3, gbuf + bufo + (uint32_t)br * 128u + ps * 16u);
                    mma_f16(acc[0][p][0], afr0, b0, b1);
                    mma_f16(acc[0][p][1], afr0, b2, b3);
                    mma_f16(acc[1][p][0], afr1, b0, b1);
                    mma_f16(acc[1][p][1], afr1, b2, b3);
                }
            }

            if (c4 == 3) {
                int nt  = 2 * kc + grp;
                int ntb = nt * 128 + wn * 64;
                #pragma unroll
                for (int p = 0; p < 4; ++p) {
                    int colb = ntb + p * 16 + (lane & 3) * 2;
                    float2 ehA = *(const float2*)(s_eh1k + colb);
                    float2 ehB = *(const float2*)(s_eh1k + colb + 8);
                    #pragma unroll
                    for (int mf = 0; mf < 2; ++mf) {
                        PACK3(mf * 2 + 0, ehA.x, acc[mf][p][0][0], colb);
                        PACK3(mf * 2 + 0, ehA.y, acc[mf][p][0][1], colb + 1);
                        PACK3(mf * 2 + 0, ehB.x, acc[mf][p][1][0], colb + 8);
                        PACK3(mf * 2 + 0, ehB.y, acc[mf][p][1][1], colb + 9);
                        PACK3(mf * 2 + 1, ehA.x, acc[mf][p][0][2], colb);
                        PACK3(mf * 2 + 1, ehA.y, acc[mf][p][0][3], colb + 1);
                        PACK3(mf * 2 + 1, ehB.x, acc[mf][p][1][2], colb + 8);
                        PACK3(mf * 2 + 1, ehB.y, acc[mf][p][1][3], colb + 9);
                    }
                }
            }
        }
    }

    // ---- reduce across the 4 lanes sharing each row ----
    #pragma unroll
    for (int sl = 0; sl < 4; ++sl) {
        int a1 = pm1[sl], a2 = pm2[sl], a3 = pm3[sl];
        #pragma unroll
        for (int o = 1; o <= 2; o <<= 1) {
            int b1 = __shfl_xor_sync(0xffffffffu, a1, o);
            int b2 = __shfl_xor_sync(0xffffffffu, a2, o);
            int b3 = __shfl_xor_sync(0xffffffffu, a3, o);
            pmerge(a1, a2, a3, b1, b2, b3);
        }
        if ((lane & 3) == 0) {
            int row = wm * 32 + (sl >> 1) * 16 + (sl & 1) * 8 + (lane >> 2);
            int ent = row * 4 + grp * 2 + wn;
            pm1s[ent] = a1; pm2s[ent] = a2; pm3s[ent] = a3;
        }
    }
    __syncthreads();

    if (tid < BM) {
        int a1 = pm1s[tid * 4], a2 = pm2s[tid * 4], a3 = pm3s[tid * 4];
        #pragma unroll
        for (int t = 1; t < 4; ++t)
            pmerge(a1, a2, a3, pm1s[tid * 4 + t], pm2s[tid * 4 + t], pm3s[tid * 4 + t]);
        int i1 = a1 & 1023;
        int i2 = a2 & 1023;
        int pairf = (a2 - a1) < THETA_FIX;
        int fullf = (a3 - a1) < THETA_FIX;
        sidx[tid]  = i1;
        sp2[tid]   = i2;
        spair[tid] = pairf && !fullf;
        sflg[tid]  = fullf;
        if (fullf) {
            int p = atomicAdd(&g_flag_cnt, 1);
            g_flag_rows[p] = rowbase + tid;
        } else if (!pairf) {
            atomicAdd(&g_counts[i1], 1.0f);
        }
    }
    __syncthreads();

    // ---- in-kernel pair resolve: warp-per-row exact fp32 compare {i1, i2} ----
    #pragma unroll 1
    for (int r = w; r < BM; r += 16) {
        if (!spair[r]) continue;
        const float4* zr = (const float4*)(z + (size_t)(rowbase + r) * D);
        float4 za = zr[lane];
        float4 zc = zr[lane + 32];
        int c0 = sidx[r], c1 = sp2[r];
        const float4* e0 = (const float4*)(e + (size_t)c0 * D);
        const float4* e1 = (const float4*)(e + (size_t)c1 * D);
        float4 a0 = e0[lane], b0 = e0[lane + 32];
        float4 a1 = e1[lane], b1 = e1[lane + 32];
        float d0 = a0.x*za.x + a0.y*za.y + a0.z*za.z + a0.w*za.w
                 + b0.x*zc.x + b0.y*zc.y + b0.z*zc.z + b0.w*zc.w;
        float d1 = a1.x*za.x + a1.y*za.y + a1.z*za.z + a1.w*za.w
                 + b1.x*zc.x + b1.y*zc.y + b1.z*zc.z + b1.w*zc.w;
        #pragma unroll
        for (int o = 16; o > 0; o >>= 1) {
            d0 += __shfl_xor_sync(0xffffffffu, d0, o);
            d1 += __shfl_xor_sync(0xffffffffu, d1, o);
        }
        if (lane == 0) {
            float s0 = s_eh[c0] - d0;
            float s1 = s_eh[c1] - d1;
            int best = (s1 < s0 || (s1 == s0 && c1 < c0)) ? c1 : c0;
            sidx[r] = best;
            atomicAdd(&g_counts[best], 1.0f);
        }
    }
    __syncthreads();

    // ---- fused output: gather + loss for all non-full rows ----
    float lacc = 0.0f;
    #pragma unroll 4
    for (int p = tid; p < BM * D; p += 512) {
        int r = p >> 8;
        int cc = p & 255;
        if (!sflg[r]) {
            float q  = e[(size_t)sidx[r] * D + cc];
            float zv = z[(size_t)(rowbase + r) * D + cc];
            outq[(size_t)(rowbase + r) * D + cc] = q;
            float d = q - zv;
            lacc += d * d;
        }
    }
    red[tid] = lacc;
    __syncthreads();
    for (int o = 256; o > 32; o >>= 1) {
        if (tid < o) red[tid] += red[tid + o];
        __syncthreads();
    }
    if (tid < 32) {
        float v = red[tid] + red[tid + 32];
        #pragma unroll
        for (int o = 16; o > 0; o >>= 1) v += __shfl_down_sync(0xffffffffu, v, o);
        if (tid == 0) atomicAdd(&g_loss, (double)v);
    }
}

// full exact fp32 rescan, BLOCK-per-row (8 warps x 128 codes, ILP2); rare rows only
__global__ __launch_bounds__(256) void rescue_full(const float* __restrict__ z,
                                                   const float* __restrict__ e,
                                                   float* __restrict__ outq) {
    __shared__ float zs[256];
    __shared__ float rbv[8];
    __shared__ int   rbi[8];
    __shared__ int   s_best;
    __shared__ float red[256];
    int cnt = g_flag_cnt;
    int tid = threadIdx.x, w = tid >> 5, lane = tid & 31;
    for (int ri = blockIdx.x; ri < cnt; ri += gridDim.x) {
        int row = g_flag_rows[ri];
        if (tid < 64) ((float4*)zs)[tid] = ((const float4*)(z + (size_t)row * D))[tid];
        __syncthreads();
        float4 za = ((const float4*)zs)[lane];
        float4 zc = ((const float4*)zs)[lane + 32];

        float bm = __int_as_float(0x7f800000);
        int   bi = KCODES;
        int wbase = w * 128;
        #pragma unroll 1
        for (int k = 0; k < 128; k += 2) {
            int c0 = wbase + k, c1 = c0 + 1;
            const float4* e0 = (const float4*)(e + (size_t)c0 * D);
            const float4* e1 = (const float4*)(e + (size_t)c1 * D);
            float4 a0 = e0[lane], b0 = e0[lane + 32];
            float4 a1 = e1[lane], b1 = e1[lane + 32];
            float d0 = a0.x*za.x + a0.y*za.y + a0.z*za.z + a0.w*za.w
                     + b0.x*zc.x + b0.y*zc.y + b0.z*zc.z + b0.w*zc.w;
            float d1 = a1.x*za.x + a1.y*za.y + a1.z*za.z + a1.w*za.w
                     + b1.x*zc.x + b1.y*zc.y + b1.z*zc.z + b1.w*zc.w;
            #pragma unroll
            for (int o = 16; o > 0; o >>= 1) {
                d0 += __shfl_xor_sync(0xffffffffu, d0, o);
                d1 += __shfl_xor_sync(0xffffffffu, d1, o);
            }
            float s0 = g_e_half[c0] - d0;
            float s1 = g_e_half[c1] - d1;
            if (s0 < bm) { bm = s0; bi = c0; }
            if (s1 < bm) { bm = s1; bi = c1; }
        }
        if (lane == 0) { rbv[w] = bm; rbi[w] = bi; }
        __syncthreads();
        if (tid == 0) {
            float bv = rbv[0]; int bb = rbi[0];
            #pragma unroll
            for (int j = 1; j < 8; ++j)
                if (rbv[j] < bv || (rbv[j] == bv && rbi[j] < bb)) { bv = rbv[j]; bb = rbi[j]; }
            s_best = bb;
            atomicAdd(&g_counts[bb], 1.0f);
        }
        __syncthreads();
        int best = s_best;
        float q  = e[(size_t)best * D + tid];
        float dv = q - zs[tid];
        outq[(size_t)row * D + tid] = q;
        red[tid] = dv * dv;
        __syncthreads();
        for (int o = 128; o > 32; o >>= 1) {
            if (tid < o) red[tid] += red[tid + o];
            __syncthreads();
        }
        if (tid < 32) {
            float v = red[tid] + red[tid + 32];
            #pragma unroll
            for (int o = 16; o > 0; o >>= 1) v += __shfl_down_sync(0xffffffffu, v, o);
            if (tid == 0) atomicAdd(&g_loss, (double)v);
        }
        __syncthreads();
    }
}

__global__ void finalize_kernel(float* __restrict__ out, int N) {
    __shared__ float red[1024];
    int t = threadIdx.x;
    float p = g_counts[t] * (1.0f / (float)N);
    red[t] = p * logf(p + 1e-10f);
    __syncthreads();
    for (int o = 512; o > 0; o >>= 1) {
        if (t < o) red[t] += red[t + o];
        __syncthreads();
    }
    if (t == 0) {
        out[0] = 0.25f * (float)(g_loss / ((double)N * (double)D));
        out[(size_t)N * D + 1] = expf(-red[0]);
    }
}

// ---------------------------------------------------------------------------
extern "C" void kernel_launch(void* const* d_in, const int* in_sizes, int n_in,
                              void* d_out, int out_size) {
    const float* z = (const float*)d_in[0];   // z_e  [N, 256]
    const float* e = (const float*)d_in[1];   // emb  [1024, 256]
    float* out = (float*)d_out;               // [loss, quantized(N*256), perplexity]
    int N = in_sizes[0] / D;                  // 131072

    cudaFuncSetAttribute(vq_main, cudaFuncAttributeMaxDynamicSharedMemorySize, DYN_SMEM);

    // two no-op launches so vq_main stays at absolute launch index 3 (ncu window)
    noop_kernel<<<1, 32>>>();
    noop_kernel<<<1, 32>>>();
    prep_kernel<<<(KCODES * 32) / 256, 256>>>(e);
    vq_main<<<N / BM, 512, DYN_SMEM>>>(z, e, out + 1);
    rescue_full<<<1024, 256>>>(z, e, out + 1);
    finalize_kernel<<<1, 1024>>>(out, N);
}

// round 14
// speedup vs baseline: 2.0136x; 1.0088x over previous
#include <cuda_runtime.h>
#include <cuda_fp16.h>
#include <cstdint>

#define D        256
#define KCODES   1024
#define BM       128
#define THETA_FIX 83886      // 0.08 * 2^20
#define DYN_SMEM 216064

// ---- device scratch (no allocations allowed) ----
__device__ uint32_t g_epack[KCODES * 128];   // per code: 256 fp16 (512B row)
__device__ float    g_e_half[KCODES];
__device__ float    g_counts[KCODES];
__device__ int      g_flag_rows[131072];     // rows needing full fp32 rescan
__device__ int      g_flag_cnt;
__device__ double   g_loss;

// ============================ helpers ============================
__device__ __forceinline__ uint32_t smem_u32(const void* p) {
    uint32_t a;
    asm("{ .reg .u64 t; cvta.to.shared.u64 t, %1; cvt.u32.u64 %0, t; }" : "=r"(a) : "l"(p));
    return a;
}

__device__ __forceinline__ void ldsm_x4(uint32_t& r0, uint32_t& r1, uint32_t& r2, uint32_t& r3,
                                        uint32_t addr) {
    asm volatile("ldmatrix.sync.aligned.m8n8.x4.shared.b16 {%0,%1,%2,%3}, [%4];"
                 : "=r"(r0), "=r"(r1), "=r"(r2), "=r"(r3) : "r"(addr));
}

__device__ __forceinline__ void mma_f16(float* c, const uint32_t* a, uint32_t b0, uint32_t b1) {
    asm volatile("mma.sync.aligned.m16n8k16.row.col.f32.f16.f16.f32 "
                 "{%0,%1,%2,%3}, {%4,%5,%6,%7}, {%8,%9}, {%0,%1,%2,%3};"
                 : "+f"(c[0]), "+f"(c[1]), "+f"(c[2]), "+f"(c[3])
                 : "r"(a[0]), "r"(a[1]), "r"(a[2]), "r"(a[3]), "r"(b0), "r"(b1));
}

#define CP_ASYNC16(dst, src) \
    asm volatile("cp.async.cg.shared.global [%0], [%1], 16;" :: "r"(dst), "l"(src) : "memory")
#define CP_COMMIT() asm volatile("cp.async.commit_group;" ::: "memory")
#define CP_WAIT0() asm volatile("cp.async.wait_group 0;" ::: "memory")
#define BAR_GRP(id) asm volatile("bar.sync %0, 256;" :: "r"(id) : "memory")

// branchless top-3 insert of packed int x (score*2^20 | col), sorted pm1<=pm2<=pm3
#define PACK3(sl, ehv, accv, col) do { \
    int _si = __float2int_rz(fmaf((accv), -1024.0f, (ehv))); \
    int _x  = _si * 1024 + (col); \
    pm3[sl] = min(pm3[sl], max(pm2[sl], _x)); \
    pm2[sl] = min(pm2[sl], max(pm1[sl], _x)); \
    pm1[sl] = min(pm1[sl], _x); \
} while (0)

// merge two sorted top-3 triples (8 min/max ops)
__device__ __forceinline__ void pmerge(int& a1, int& a2, int& a3, int b1, int b2, int b3) {
    int t1  = max(a1, b1);
    a1      = min(a1, b1);
    int m22 = min(a2, b2);
    int M22 = max(a2, b2);
    a2      = min(t1, m22);
    a3      = min(min(a3, b3), min(max(t1, m22), M22));
}

// ============================ kernels ============================
__global__ void noop_kernel() {}

// One warp per code: pack 256 fp16 + 0.5*||e||^2 ; also reset globals
__global__ void prep_kernel(const float* __restrict__ e) {
    int tid  = threadIdx.x;
    int gw   = (blockIdx.x * blockDim.x + tid) >> 5;
    int lane = tid & 31;
    if (blockIdx.x < 4) g_counts[blockIdx.x * 256 + tid] = 0.0f;
    if (blockIdx.x == 0 && tid == 0) { g_loss = 0.0; g_flag_cnt = 0; }
    if (gw >= KCODES) return;
    const float4* er = (const float4*)(e + (size_t)gw * D);
    float4 a = er[lane * 2];
    float4 b = er[lane * 2 + 1];
    __half2 h0 = __floats2half2_rn(a.x, a.y);
    __half2 h1 = __floats2half2_rn(a.z, a.w);
    __half2 h2 = __floats2half2_rn(b.x, b.y);
    __half2 h3 = __floats2half2_rn(b.z, b.w);
    uint4 u;
    u.x = *(uint32_t*)&h0; u.y = *(uint32_t*)&h1;
    u.z = *(uint32_t*)&h2; u.w = *(uint32_t*)&h3;
    *(uint4*)&g_epack[gw * 128 + lane * 4] = u;
    float s = a.x*a.x + a.y*a.y + a.z*a.z + a.w*a.w
            + b.x*b.x + b.y*b.y + b.z*b.z + b.w*b.w;
    #pragma unroll
    for (int o = 16; o > 0; o >>= 1) s += __shfl_down_sync(0xffffffffu, s, o);
    if (lane == 0) g_e_half[gw] = 0.5f * s;
}

// issue cp.asyncs for one 16KB sub-chunk (128 codes x 128B k-slice), no commit
__device__ __forceinline__ void load_chunk_body(uint32_t dstb, int nt, int c, int gtid) {
    const char* src0 = (const char*)g_epack + (size_t)nt * 65536 + (size_t)c * 128;
    #pragma unroll
    for (int it = 0; it < 4; ++it) {
        int i = it * 256 + gtid;          // 1024 16B units
        int r = i >> 3, s = i & 7;
        uint32_t ps = (uint32_t)s ^ ((uint32_t)r & 7u);
        CP_ASYNC16(dstb + (uint32_t)r * 128u + ps * 16u, src0 + (size_t)r * 512 + s * 16);
    }
}

__global__ __launch_bounds__(512, 1) void vq_main(const float* __restrict__ z,
                                                  const float* __restrict__ e,
                                                  float* __restrict__ outq) {
    extern __shared__ char dsm[];
    char* base = (char*)(((uintptr_t)dsm + 1023) & ~(uintptr_t)1023);
    char*  sA      = base;                     // 65536 : 128 rows x 256 fp16 (swizzled)
    char*  sB      = base + 65536;             // 2 groups x 2 bufs x 32768
    float* s_eh    = (float*)(base + 196608);  // 1024 f  (exact 0.5||e||^2)
    float* s_eh1k  = (float*)(base + 200704);  // 1024 f  (x1024)
    int*   pm1s    = (int*)  (base + 204800);  // 128 x 4
    int*   pm2s    = (int*)  (base + 206848);
    int*   pm3s    = (int*)  (base + 208896);
    int*   sidx    = (int*)  (base + 210944);  // 128
    int*   sp2     = (int*)  (base + 211456);  // 128
    int*   spair   = (int*)  (base + 211968);  // 128
    int*   sflg    = (int*)  (base + 212480);  // 128
    float* red     = (float*)(base + 212992);  // 512 f

    const int tid  = threadIdx.x;
    const int lane = tid & 31;
    const int w    = tid >> 5;
    const int grp  = w >> 3;        // 0/1 : independent pipeline
    const int gtid = tid & 255;
    const int wm   = (w & 7) >> 1;  // 0..3 : M warp (32 rows)
    const int wn   = w & 1;         // 0..1 : N warp (64 cols)
    const int rowbase = blockIdx.x * BM;
    const uint32_t sAu = smem_u32(sA);
    const uint32_t gbuf = smem_u32(sB) + (uint32_t)grp * 65536u;

    // prologue: chunk 0 of this group = nt=grp, k-slices 0,1 -> buf 0 (32KB)
    load_chunk_body(gbuf,          grp, 0, gtid);
    load_chunk_body(gbuf + 16384u, grp, 1, gtid);
    CP_COMMIT();

    for (int i = tid; i < KCODES; i += 512) {
        float v = g_e_half[i];
        s_eh[i]   = v;
        s_eh1k[i] = v * 1024.0f;
    }

    // ---- convert this CTA's 128 z rows into swizzled fp16 SMEM A ----
    const float4* zb = (const float4*)(z + (size_t)rowbase * D);
    #pragma unroll
    for (int i = 0; i < 16; ++i) {
        int idx = i * 512 + tid;           // 8192 float4s
        int r = idx >> 6, f = idx & 63;
        float4 v = zb[r * 64 + f];
        __half2 p0 = __floats2half2_rn(v.x, v.y);
        __half2 p1 = __floats2half2_rn(v.z, v.w);
        uint2 u; u.x = *(uint32_t*)&p0; u.y = *(uint32_t*)&p1;
        uint32_t seg = (uint32_t)(f >> 1);
        uint32_t ps = (seg & ~7u) | ((seg & 7u) ^ ((uint32_t)r & 7u));
        *(uint2*)(sA + (size_t)r * 512 + ps * 16 + (f & 1) * 8) = u;
    }
    __syncthreads();   // sA + eh tables visible to both groups

    int pm1[4], pm2[4], pm3[4];
    #pragma unroll
    for (int s = 0; s < 4; ++s) { pm1[s] = 0x7FFFFFFF; pm2[s] = 0x7FFFFFFF; pm3[s] = 0x7FFFFFFF; }

    float acc[2][4][2][4];

    // ---- per-group pipeline: 8 chunks of 32KB (4 nt x 2 halves) ----
    #pragma unroll 1
    for (int kk = 0; kk < 4; ++kk) {
        #pragma unroll
        for (int half = 0; half < 2; ++half) {
            if (half == 0) {
                #pragma unroll
                for (int a = 0; a < 2; ++a)
                    #pragma unroll
                    for (int p = 0; p < 4; ++p)
                        #pragma unroll
                        for (int q = 0; q < 2; ++q)
                            #pragma unroll
                            for (int x = 0; x < 4; ++x) acc[a][p][q][x] = 0.0f;
            }
            CP_WAIT0();              // chunk k = kk*2+half arrived
            BAR_GRP(grp + 1);        // collective visibility; other buf free
            {
                int k = kk * 2 + half;
                if (k < 7) {
                    int kn  = k + 1;
                    int ntn = 2 * (kn >> 1) + grp;
                    int hn  = kn & 1;
                    uint32_t db = gbuf + (uint32_t)(hn * 32768);
                    load_chunk_body(db,          ntn, 2 * hn,     gtid);
                    load_chunk_body(db + 16384u, ntn, 2 * hn + 1, gtid);
                }
                CP_COMMIT();         // always commit (possibly empty)
            }

            const uint32_t bufo = (uint32_t)(half * 32768);   // compile-time

            #pragma unroll
            for (int c2 = 0; c2 < 2; ++c2) {
                #pragma unroll
                for (int ks = 0; ks < 4; ++ks) {
                    uint32_t afr0[4], afr1[4];
                    {
                        uint32_t seg = (uint32_t)((2 * half + c2) * 8 + ks * 2)
                                     + (uint32_t)(lane >> 4);
                        int ar0 = wm * 32 + (lane & 15);
                        int ar1 = ar0 + 16;
                        uint32_t ps0 = (seg & ~7u) | ((seg & 7u) ^ ((uint32_t)ar0 & 7u));
                        uint32_t ps1 = (seg & ~7u) | ((seg & 7u) ^ ((uint32_t)ar1 & 7u));
                        ldsm_x4(afr0[0], afr0[1], afr0[2], afr0[3],
                                sAu + (uint32_t)ar0 * 512u + ps0 * 16u);
                        ldsm_x4(afr1[0], afr1[1], afr1[2], afr1[3],
                                sAu + (uint32_t)ar1 * 512u + ps1 * 16u);
                    }
                    #pragma unroll
                    for (int p = 0; p < 4; ++p) {
                        int br = wn * 64 + p * 16 + (lane & 7) + ((lane >> 4) & 1) * 8;
                        uint32_t ls = (uint32_t)(ks * 2) + (uint32_t)((lane >> 3) & 1);
                        uint32_t ps = ls ^ ((uint32_t)br & 7u);
                        uint32_t b0, b1, b2, b3;
                        ldsm_x4(b0, b1, b2, b3,
                                gbuf + bufo + (uint32_t)(c2 * 16384) +
                                (uint32_t)br * 128u + ps * 16u);
                        mma_f16(acc[0][p][0], afr0, b0, b1);
                        mma_f16(acc[0][p][1], afr0, b2, b3);
                        mma_f16(acc[1][p][0], afr1, b0, b1);
                        mma_f16(acc[1][p][1], afr1, b2, b3);
                    }
                }
            }

            if (half == 1) {
                int nt  = 2 * kk + grp;
                int ntb = nt * 128 + wn * 64;
                #pragma unroll
                for (int p = 0; p < 4; ++p) {
                    int colb = ntb + p * 16 + (lane & 3) * 2;
                    float2 ehA = *(const float2*)(s_eh1k + colb);
                    float2 ehB = *(const float2*)(s_eh1k + colb + 8);
                    #pragma unroll
                    for (int mf = 0; mf < 2; ++mf) {
                        PACK3(mf * 2 + 0, ehA.x, acc[mf][p][0][0], colb);
                        PACK3(mf * 2 + 0, ehA.y, acc[mf][p][0][1], colb + 1);
                        PACK3(mf * 2 + 0, ehB.x, acc[mf][p][1][0], colb + 8);
                        PACK3(mf * 2 + 0, ehB.y, acc[mf][p][1][1], colb + 9);
                        PACK3(mf * 2 + 1, ehA.x, acc[mf][p][0][2], colb);
                        PACK3(mf * 2 + 1, ehA.y, acc[mf][p][0][3], colb + 1);
                        PACK3(mf * 2 + 1, ehB.x, acc[mf][p][1][2], colb + 8);
                        PACK3(mf * 2 + 1, ehB.y, acc[mf][p][1][3], colb + 9);
                    }
                }
            }
        }
    }

    // ---- reduce across the 4 lanes sharing each row ----
    #pragma unroll
    for (int sl = 0; sl < 4; ++sl) {
        int a1 = pm1[sl], a2 = pm2[sl], a3 = pm3[sl];
        #pragma unroll
        for (int o = 1; o <= 2; o <<= 1) {
            int b1 = __shfl_xor_sync(0xffffffffu, a1, o);
            int b2 = __shfl_xor_sync(0xffffffffu, a2, o);
            int b3 = __shfl_xor_sync(0xffffffffu, a3, o);
            pmerge(a1, a2, a3, b1, b2, b3);
        }
        if ((lane & 3) == 0) {
            int row = wm * 32 + (sl >> 1) * 16 + (sl & 1) * 8 + (lane >> 2);
            int ent = row * 4 + grp * 2 + wn;
            pm1s[ent] = a1; pm2s[ent] = a2; pm3s[ent] = a3;
        }
    }
    __syncthreads();

    if (tid < BM) {
        int a1 = pm1s[tid * 4], a2 = pm2s[tid * 4], a3 = pm3s[tid * 4];
        #pragma unroll
        for (int t = 1; t < 4; ++t)
            pmerge(a1, a2, a3, pm1s[tid * 4 + t], pm2s[tid * 4 + t], pm3s[tid * 4 + t]);
        int i1 = a1 & 1023;
        int i2 = a2 & 1023;
        int pairf = (a2 - a1) < THETA_FIX;
        int fullf = (a3 - a1) < THETA_FIX;
        sidx[tid]  = i1;
        sp2[tid]   = i2;
        spair[tid] = pairf && !fullf;
        sflg[tid]  = fullf;
        if (fullf) {
            int p = atomicAdd(&g_flag_cnt, 1);
            g_flag_rows[p] = rowbase + tid;
        } else if (!pairf) {
            atomicAdd(&g_counts[i1], 1.0f);
        }
    }
    __syncthreads();

    // ---- in-kernel pair resolve: warp-per-row exact fp32 compare {i1, i2} ----
    #pragma unroll 1
    for (int r = w; r < BM; r += 16) {
        if (!spair[r]) continue;
        const float4* zr = (const float4*)(z + (size_t)(rowbase + r) * D);
        float4 za = zr[lane];
        float4 zc = zr[lane + 32];
        int c0 = sidx[r], c1 = sp2[r];
        const float4* e0 = (const float4*)(e + (size_t)c0 * D);
        const float4* e1 = (const float4*)(e + (size_t)c1 * D);
        float4 a0 = e0[lane], b0 = e0[lane + 32];
        float4 a1 = e1[lane], b1 = e1[lane + 32];
        float d0 = a0.x*za.x + a0.y*za.y + a0.z*za.z + a0.w*za.w
                 + b0.x*zc.x + b0.y*zc.y + b0.z*zc.z + b0.w*zc.w;
        float d1 = a1.x*za.x + a1.y*za.y + a1.z*za.z + a1.w*za.w
                 + b1.x*zc.x + b1.y*zc.y + b1.z*zc.z + b1.w*zc.w;
        #pragma unroll
        for (int o = 16; o > 0; o >>= 1) {
            d0 += __shfl_xor_sync(0xffffffffu, d0, o);
            d1 += __shfl_xor_sync(0xffffffffu, d1, o);
        }
        if (lane == 0) {
            float s0 = s_eh[c0] - d0;
            float s1 = s_eh[c1] - d1;
            int best = (s1 < s0 || (s1 == s0 && c1 < c0)) ? c1 : c0;
            sidx[r] = best;
            atomicAdd(&g_counts[best], 1.0f);
        }
    }
    __syncthreads();

    // ---- fused output: gather + loss for all non-full rows ----
    float lacc = 0.0f;
    #pragma unroll 4
    for (int p = tid; p < BM * D; p += 512) {
        int r = p >> 8;
        int cc = p & 255;
        if (!sflg[r]) {
            float q  = e[(size_t)sidx[r] * D + cc];
            float zv = z[(size_t)(rowbase + r) * D + cc];
            outq[(size_t)(rowbase + r) * D + cc] = q;
            float d = q - zv;
            lacc += d * d;
        }
    }
    red[tid] = lacc;
    __syncthreads();
    for (int o = 256; o > 32; o >>= 1) {
        if (tid < o) red[tid] += red[tid + o];
        __syncthreads();
    }
    if (tid < 32) {
        float v = red[tid] + red[tid + 32];
        #pragma unroll
        for (int o = 16; o > 0; o >>= 1) v += __shfl_down_sync(0xffffffffu, v, o);
        if (tid == 0) atomicAdd(&g_loss, (double)v);
    }
}

// full exact fp32 rescan, BLOCK-per-row (8 warps x 128 codes, ILP2); rare rows only
__global__ __launch_bounds__(256) void rescue_full(const float* __restrict__ z,
                                                   const float* __restrict__ e,
                                                   float* __restrict__ outq) {
    __shared__ float zs[256];
    __shared__ float rbv[8];
    __shared__ int   rbi[8];
    __shared__ int   s_best;
    __shared__ float red[256];
    int cnt = g_flag_cnt;
    int tid = threadIdx.x, w = tid >> 5, lane = tid & 31;
    for (int ri = blockIdx.x; ri < cnt; ri += gridDim.x) {
        int row = g_flag_rows[ri];
        if (tid < 64) ((float4*)zs)[tid] = ((const float4*)(z + (size_t)row * D))[tid];
        __syncthreads();
        float4 za = ((const float4*)zs)[lane];
        float4 zc = ((const float4*)zs)[lane + 32];

        float bm = __int_as_float(0x7f800000);
        int   bi = KCODES;
        int wbase = w * 128;
        #pragma unroll 1
        for (int k = 0; k < 128; k += 2) {
            int c0 = wbase + k, c1 = c0 + 1;
            const float4* e0 = (const float4*)(e + (size_t)c0 * D);
            const float4* e1 = (const float4*)(e + (size_t)c1 * D);
            float4 a0 = e0[lane], b0 = e0[lane + 32];
            float4 a1 = e1[lane], b1 = e1[lane + 32];
            float d0 = a0.x*za.x + a0.y*za.y + a0.z*za.z + a0.w*za.w
                     + b0.x*zc.x + b0.y*zc.y + b0.z*zc.z + b0.w*zc.w;
            float d1 = a1.x*za.x + a1.y*za.y + a1.z*za.z + a1.w*za.w
                     + b1.x*zc.x + b1.y*zc.y + b1.z*zc.z + b1.w*zc.w;
            #pragma unroll
            for (int o = 16; o > 0; o >>= 1) {
                d0 += __shfl_xor_sync(0xffffffffu, d0, o);
                d1 += __shfl_xor_sync(0xffffffffu, d1, o);
            }
            float s0 = g_e_half[c0] - d0;
            float s1 = g_e_half[c1] - d1;
            if (s0 < bm) { bm = s0; bi = c0; }
            if (s1 < bm) { bm = s1; bi = c1; }
        }
        if (lane == 0) { rbv[w] = bm; rbi[w] = bi; }
        __syncthreads();
        if (tid == 0) {
            float bv = rbv[0]; int bb = rbi[0];
            #pragma unroll
            for (int j = 1; j < 8; ++j)
                if (rbv[j] < bv || (rbv[j] == bv && rbi[j] < bb)) { bv = rbv[j]; bb = rbi[j]; }
            s_best = bb;
            atomicAdd(&g_counts[bb], 1.0f);
        }
        __syncthreads();
        int best = s_best;
        float q  = e[(size_t)best * D + tid];
        float dv = q - zs[tid];
        outq[(size_t)row * D + tid] = q;
        red[tid] = dv * dv;
        __syncthreads();
        for (int o = 128; o > 32; o >>= 1) {
            if (tid < o) red[tid] += red[tid + o];
            __syncthreads();
        }
        if (tid < 32) {
            float v = red[tid] + red[tid + 32];
            #pragma unroll
            for (int o = 16; o > 0; o >>= 1) v += __shfl_down_sync(0xffffffffu, v, o);
            if (tid == 0) atomicAdd(&g_loss, (double)v);
        }
        __syncthreads();
    }
}

__global__ void finalize_kernel(float* __restrict__ out, int N) {
    __shared__ float red[1024];
    int t = threadIdx.x;
    float p = g_counts[t] * (1.0f / (float)N);
    red[t] = p * logf(p + 1e-10f);
    __syncthreads();
    for (int o = 512; o > 0; o >>= 1) {
        if (t < o) red[t] += red[t + o];
        __syncthreads();
    }
    if (t == 0) {
        out[0] = 0.25f * (float)(g_loss / ((double)N * (double)D));
        out[(size_t)N * D + 1] = expf(-red[0]);
    }
}

// ---------------------------------------------------------------------------
extern "C" void kernel_launch(void* const* d_in, const int* in_sizes, int n_in,
                              void* d_out, int out_size) {
    const float* z = (const float*)d_in[0];   // z_e  [N, 256]
    const float* e = (const float*)d_in[1];   // emb  [1024, 256]
    float* out = (float*)d_out;               // [loss, quantized(N*256), perplexity]
    int N = in_sizes[0] / D;                  // 131072

    cudaFuncSetAttribute(vq_main, cudaFuncAttributeMaxDynamicSharedMemorySize, DYN_SMEM);

    // two no-op launches so vq_main stays at absolute launch index 3 (ncu window)
    noop_kernel<<<1, 32>>>();
    noop_kernel<<<1, 32>>>();
    prep_kernel<<<(KCODES * 32) / 256, 256>>>(e);
    vq_main<<<N / BM, 512, DYN_SMEM>>>(z, e, out + 1);
    rescue_full<<<1024, 256>>>(z, e, out + 1);
    finalize_kernel<<<1, 1024>>>(out, N);
}